// round 3
// baseline (speedup 1.0000x reference)
#include <cuda_runtime.h>
#include <cuda_bf16.h>
#include <cstdint>

typedef __nv_bfloat16 bf16;

#define Bx 4
#define Sx 2048
#define Hx 1024
#define Mx 8192            // B*S
#define CH 128             // scan chunk length
#define NCH 16             // S / CH

// ---------------- device scratch ----------------
__device__ __align__(256) bf16  g_Xhi[Mx * Hx];
__device__ __align__(256) bf16  g_Xlo[Mx * Hx];
__device__ __align__(256) bf16  g_Whi[3 * Hx * Hx];   // [Wi, Wf, Wg]
__device__ __align__(256) bf16  g_Wlo[3 * Hx * Hx];
__device__ __align__(256) bf16  g_Wohi[Hx * Hx];
__device__ __align__(256) bf16  g_Wolo[Hx * Hx];
__device__ __align__(256) float g_Yi[Mx * Hx];        // i_raw -> local h (in place)
__device__ __align__(256) float g_Yf[Mx * Hx];        // f_raw -> cumprod (in place)
__device__ __align__(256) float g_Yg[Mx * Hx];        // g (raw)
__device__ __align__(256) bf16  g_GHhi[Mx * Hx];
__device__ __align__(256) bf16  g_GHlo[Mx * Hx];
__device__ float g_P[Bx * NCH * Hx];
__device__ float g_E[Bx * NCH * Hx];
__device__ float g_Cr[Bx * NCH * Hx];

// ---------------- PTX helpers ----------------
__device__ __forceinline__ uint32_t smem_u32(const void* p) {
    uint32_t a;
    asm("{ .reg .u64 t; cvta.to.shared.u64 t, %1; cvt.u32.u64 %0, t; }" : "=r"(a) : "l"(p));
    return a;
}

__device__ __forceinline__ void ldsm_x4(uint32_t& r0, uint32_t& r1, uint32_t& r2,
                                        uint32_t& r3, uint32_t addr) {
    asm volatile("ldmatrix.sync.aligned.m8n8.x4.shared.b16 {%0,%1,%2,%3}, [%4];"
                 : "=r"(r0), "=r"(r1), "=r"(r2), "=r"(r3) : "r"(addr));
}

__device__ __forceinline__ void mma_bf16(float* c, const uint32_t* a, const uint32_t* b) {
    asm volatile(
        "mma.sync.aligned.m16n8k16.row.col.f32.bf16.bf16.f32 "
        "{%0,%1,%2,%3}, {%4,%5,%6,%7}, {%8,%9}, {%0,%1,%2,%3};"
        : "+f"(c[0]), "+f"(c[1]), "+f"(c[2]), "+f"(c[3])
        : "r"(a[0]), "r"(a[1]), "r"(a[2]), "r"(a[3]), "r"(b[0]), "r"(b[1]));
}

// ---------------- GEMM: C[M,N] = A[M,K] @ W[N,K]^T, bf16x3-split, fp32 out ---
// CTA tile 128x128, K-chunk 64, 3-stage cp.async pipeline (single sync/iter,
// loads issued 2 iters ahead), 8 warps (2x4), warp tile 64x32, frag double-buf.
#define STAGE_BYTES 65536u          // 4 tiles x (128 x 64 bf16) = 4 x 16KB
#define GEMM_SMEM   (1024 + 3 * 65536)

__device__ __forceinline__ void load_tile(uint32_t tb, const bf16* __restrict__ src,
                                          int row0, int k0, int tid) {
    const char* gbase = (const char*)(src + (size_t)row0 * Hx + k0);
#pragma unroll
    for (int i = 0; i < 4; i++) {
        int gid = tid + i * 256;        // 1024 granules of 16B
        int row = gid >> 3;
        int g   = gid & 7;
        const char* gp = gbase + (size_t)row * (Hx * 2) + g * 16;
        uint32_t sp = tb + (uint32_t)(row * 128) + (uint32_t)((g ^ (row & 7)) << 4);
        asm volatile("cp.async.cg.shared.global [%0], [%1], 16;"
                     :: "r"(sp), "l"(gp) : "memory");
    }
}

__global__ void __launch_bounds__(256, 1) k_gemm(
    const bf16* __restrict__ Ah, const bf16* __restrict__ Al,
    const bf16* __restrict__ Bh_, const bf16* __restrict__ Bl_,
    float* __restrict__ C0, float* __restrict__ C1, float* __restrict__ C2,
    int zstride)
{
    extern __shared__ char smem_raw[];
    uint32_t sb     = smem_u32(smem_raw);
    uint32_t stage0 = (sb + 1023u) & ~1023u;

    const int tid = threadIdx.x;
    const int wid = tid >> 5;
    const int lid = tid & 31;
    const int wr  = wid >> 2;       // 0-1  -> m offset wr*64
    const int wc  = wid & 3;        // 0-3  -> n offset wc*32
    const int n0  = blockIdx.x * 128;
    const int m0  = blockIdx.y * 128;
    const int z   = blockIdx.z;
    const bf16* Bh = Bh_ + (size_t)z * zstride;
    const bf16* Bl = Bl_ + (size_t)z * zstride;
    float* C = (z == 0) ? C0 : ((z == 1) ? C1 : C2);

    // prologue: fill stages 0,1
#pragma unroll
    for (int s = 0; s < 2; s++) {
        uint32_t st = stage0 + s * STAGE_BYTES;
        load_tile(st,          Ah, m0, s * 64, tid);
        load_tile(st + 16384u, Al, m0, s * 64, tid);
        load_tile(st + 32768u, Bh, n0, s * 64, tid);
        load_tile(st + 49152u, Bl, n0, s * 64, tid);
        asm volatile("cp.async.commit_group;" ::: "memory");
    }

    float acc[4][4][4];
#pragma unroll
    for (int a = 0; a < 4; a++)
#pragma unroll
        for (int b = 0; b < 4; b++)
#pragma unroll
            for (int c = 0; c < 4; c++) acc[a][b][c] = 0.f;

    // ldmatrix address components (within a 128-row x 64-col bf16 tile,
    // 128B/row, 8 16B colgroups, XOR-swizzled).  (r&7) is invariant across
    // mt/nt/ks, so precompute row-base offsets + one swizzle constant each.
    const int aRow = lid & 15;
    const int aCg  = lid >> 4;
    const int bRow = (lid & 7) | ((lid & 16) >> 1);
    const int bCg  = (lid >> 3) & 1;
    const uint32_t aSwz = (uint32_t)(aRow & 7);
    const uint32_t bSwz = (uint32_t)(bRow & 7);
    uint32_t aOff[4], bOff[2];
#pragma unroll
    for (int mt = 0; mt < 4; mt++) aOff[mt] = (uint32_t)((wr * 64 + mt * 16 + aRow) * 128);
#pragma unroll
    for (int nt = 0; nt < 2; nt++) bOff[nt] = (uint32_t)((wc * 32 + nt * 16 + bRow) * 128);

    uint32_t ah[2][4][4], al[2][4][4], bhf[2][2][4], blf[2][2][4];

#define LOAD_FRAGS(buf, sbase, ks_) do {                                        \
    uint32_t soA = (uint32_t)(((2 * (ks_) + aCg) ^ aSwz) << 4);                 \
    uint32_t soB = (uint32_t)(((2 * (ks_) + bCg) ^ bSwz) << 4);                 \
    _Pragma("unroll")                                                           \
    for (int mt = 0; mt < 4; mt++) {                                            \
        uint32_t off = aOff[mt] + soA;                                          \
        ldsm_x4(ah[buf][mt][0], ah[buf][mt][1], ah[buf][mt][2], ah[buf][mt][3], \
                (sbase) + off);                                                 \
        ldsm_x4(al[buf][mt][0], al[buf][mt][1], al[buf][mt][2], al[buf][mt][3], \
                (sbase) + 16384u + off);                                        \
    }                                                                           \
    _Pragma("unroll")                                                           \
    for (int nt = 0; nt < 2; nt++) {                                            \
        uint32_t off = bOff[nt] + soB;                                          \
        ldsm_x4(bhf[buf][nt][0], bhf[buf][nt][1], bhf[buf][nt][2],              \
                bhf[buf][nt][3], (sbase) + 32768u + off);                       \
        ldsm_x4(blf[buf][nt][0], blf[buf][nt][1], blf[buf][nt][2],              \
                blf[buf][nt][3], (sbase) + 49152u + off);                       \
    }                                                                           \
} while (0)

#define COMPUTE(buf) do {                                                       \
    _Pragma("unroll")                                                           \
    for (int mt = 0; mt < 4; mt++)                                              \
        _Pragma("unroll")                                                       \
        for (int nt = 0; nt < 4; nt++) {                                        \
            const uint32_t* bh2 = &bhf[buf][nt >> 1][(nt & 1) * 2];             \
            const uint32_t* bl2 = &blf[buf][nt >> 1][(nt & 1) * 2];             \
            mma_bf16(acc[mt][nt], ah[buf][mt], bh2);                            \
            mma_bf16(acc[mt][nt], ah[buf][mt], bl2);                            \
            mma_bf16(acc[mt][nt], al[buf][mt], bh2);                            \
        }                                                                       \
} while (0)

    for (int k = 0; k < 16; k++) {
        uint32_t sbase = stage0 + (uint32_t)(k % 3) * STAGE_BYTES;

        if (k < 15) asm volatile("cp.async.wait_group 1;" ::: "memory");
        else        asm volatile("cp.async.wait_group 0;" ::: "memory");
        __syncthreads();   // everyone done computing iter k-1 -> slot (k-1)%3 free

        // issue gmem loads for stage k+2 into slot (k+2)%3 == (k-1)%3
        int kn = k + 2;
        if (kn < 16) {
            uint32_t lbase = stage0 + (uint32_t)(kn % 3) * STAGE_BYTES;
            load_tile(lbase,          Ah, m0, kn * 64, tid);
            load_tile(lbase + 16384u, Al, m0, kn * 64, tid);
            load_tile(lbase + 32768u, Bh, n0, kn * 64, tid);
            load_tile(lbase + 49152u, Bl, n0, kn * 64, tid);
            asm volatile("cp.async.commit_group;" ::: "memory");
        }

        // compute stage k with fragment double-buffering over ks
        LOAD_FRAGS(0, sbase, 0);
#pragma unroll
        for (int ks = 0; ks < 4; ks++) {
            int cur = ks & 1;
            if (ks < 3) LOAD_FRAGS((cur ^ 1), sbase, (ks + 1));
            COMPUTE(cur);
        }
    }

    // epilogue: fp32 accumulators straight to gmem
    const int g4 = lid >> 2;
    const int t4 = lid & 3;
#pragma unroll
    for (int mt = 0; mt < 4; mt++) {
        int row = m0 + wr * 64 + mt * 16 + g4;
#pragma unroll
        for (int nt = 0; nt < 4; nt++) {
            int col = n0 + wc * 32 + nt * 8 + t4 * 2;
            float2 v0 = make_float2(acc[mt][nt][0], acc[mt][nt][1]);
            float2 v1 = make_float2(acc[mt][nt][2], acc[mt][nt][3]);
            *(float2*)(C + (size_t)row * Hx + col)       = v0;
            *(float2*)(C + (size_t)(row + 8) * Hx + col) = v1;
        }
    }
}

// ---------------- small kernels ----------------
__global__ void k_split(const float* __restrict__ src, bf16* __restrict__ hi,
                        bf16* __restrict__ lo, int n) {
    int i = blockIdx.x * blockDim.x + threadIdx.x;
    if (i < n) {
        float x = src[i];
        bf16 h = __float2bfloat16(x);
        hi[i] = h;
        lo[i] = __float2bfloat16(x - __bfloat162float(h));
    }
}

// all 4 weight splits in one kernel (blockIdx.y selects the weight)
__global__ void k_splitW(const float* __restrict__ Wi, const float* __restrict__ Wf,
                         const float* __restrict__ Wg, const float* __restrict__ Wo) {
    int i = blockIdx.x * blockDim.x + threadIdx.x;
    int y = blockIdx.y;
    const float* s = (y == 0) ? Wi : (y == 1) ? Wf : (y == 2) ? Wg : Wo;
    bf16* hi = (y < 3) ? (g_Whi + (size_t)y * (Hx * Hx)) : g_Wohi;
    bf16* lo = (y < 3) ? (g_Wlo + (size_t)y * (Hx * Hx)) : g_Wolo;
    float x = s[i];
    bf16 h = __float2bfloat16(x);
    hi[i] = h;
    lo[i] = __float2bfloat16(x - __bfloat162float(h));
}

// pass 1: activation + chunk-local scan fused.
// Reads raw Yf/Yi, computes f=sigmoid(yf), inp=SiLU(yi)*(1-f), scans;
// overwrites Yf with cumprod(f), Yi with chunk-local h.
__global__ void k_scan1() {
    int tid = blockIdx.x * blockDim.x + threadIdx.x;   // B*NCH*H = 65536
    int h  = tid & (Hx - 1);
    int bc = tid >> 10;          // b*NCH + c
    int b  = bc >> 4;
    int c  = bc & (NCH - 1);
    size_t base = ((size_t)(b * Sx + c * CH)) * Hx + h;
    float p = 1.f, hl = 0.f;
#pragma unroll 4
    for (int t = 0; t < CH; t++) {
        size_t idx = base + (size_t)t * Hx;
        float yf = g_Yf[idx];
        float yi = g_Yi[idx];
        float f  = 1.f / (1.f + __expf(-yf));
        float s  = 1.f / (1.f + __expf(-yi));
        float in = yi * s * (1.f - f);
        hl = f * hl + in;
        p  = p * f;
        g_Yf[idx] = p;
        g_Yi[idx] = hl;
    }
    g_P[tid] = p;
    g_E[tid] = hl;
}

// pass 2: scan across chunks per channel
__global__ void k_scan2() {
    int tid = blockIdx.x * blockDim.x + threadIdx.x;   // B*H = 4096
    int h = tid & (Hx - 1);
    int b = tid >> 10;
    float carry = 0.f;
#pragma unroll
    for (int c = 0; c < NCH; c++) {
        int idx = ((b * NCH + c) << 10) + h;
        g_Cr[idx] = carry;
        carry = g_P[idx] * carry + g_E[idx];
    }
}

// pass 3: h = h_local + cumprod(f)*carry; gh = g*h; write bf16 hi/lo split
__global__ void k_scan3(int n) {
    int i = blockIdx.x * blockDim.x + threadIdx.x;
    if (i < n) {
        int h = i & (Hx - 1);
        int s = (i >> 10) & (Sx - 1);
        int b = i >> 21;
        int c = s >> 7;
        float carry = g_Cr[((b * NCH + c) << 10) + h];
        float hv = g_Yi[i] + g_Yf[i] * carry;
        float gh = g_Yg[i] * hv;
        bf16 hi = __float2bfloat16(gh);
        g_GHhi[i] = hi;
        g_GHlo[i] = __float2bfloat16(gh - __bfloat162float(hi));
    }
}

// ---------------- launch ----------------
extern "C" void kernel_launch(void* const* d_in, const int* in_sizes, int n_in,
                              void* d_out, int out_size) {
    const float* x  = (const float*)d_in[0];
    const float* Wi = (const float*)d_in[1];
    const float* Wf = (const float*)d_in[2];
    const float* Wg = (const float*)d_in[3];
    const float* Wo = (const float*)d_in[4];
    float* out = (float*)d_out;

    cudaFuncSetAttribute(k_gemm, cudaFuncAttributeMaxDynamicSharedMemorySize, GEMM_SMEM);

    bf16 *Xhi, *Xlo, *Whi, *Wlo, *Wohi, *Wolo, *GHhi, *GHlo;
    float *Yi, *Yf, *Yg;
    cudaGetSymbolAddress((void**)&Xhi,  g_Xhi);
    cudaGetSymbolAddress((void**)&Xlo,  g_Xlo);
    cudaGetSymbolAddress((void**)&Whi,  g_Whi);
    cudaGetSymbolAddress((void**)&Wlo,  g_Wlo);
    cudaGetSymbolAddress((void**)&Wohi, g_Wohi);
    cudaGetSymbolAddress((void**)&Wolo, g_Wolo);
    cudaGetSymbolAddress((void**)&GHhi, g_GHhi);
    cudaGetSymbolAddress((void**)&GHlo, g_GHlo);
    cudaGetSymbolAddress((void**)&Yi,   g_Yi);
    cudaGetSymbolAddress((void**)&Yf,   g_Yf);
    cudaGetSymbolAddress((void**)&Yg,   g_Yg);

    const int NE = Mx * Hx;     // 8388608
    const int NW = Hx * Hx;     // 1048576

    // bf16 hi/lo splits
    k_split<<<NE / 256, 256>>>(x, Xhi, Xlo, NE);
    dim3 gw(NW / 256, 4);
    k_splitW<<<gw, 256>>>(Wi, Wf, Wg, Wo);

    // GEMM1: Yi = x@Wi^T, Yf = x@Wf^T, Yg = x@Wg^T (z-fused)
    dim3 g1(Hx / 128, Mx / 128, 3);
    k_gemm<<<g1, 256, GEMM_SMEM>>>(Xhi, Xlo, Whi, Wlo, Yi, Yf, Yg, NW);

    // act + chunked linear recurrence
    k_scan1<<<(Bx * NCH * Hx) / 256, 256>>>();
    k_scan2<<<(Bx * Hx) / 256, 256>>>();
    k_scan3<<<NE / 256, 256>>>(NE);

    // GEMM2: out = (g*h) @ Wo^T
    dim3 g2(Hx / 128, Mx / 128, 1);
    k_gemm<<<g2, 256, GEMM_SMEM>>>(GHhi, GHlo, Wohi, Wolo, out, out, out, 0);
}

// round 4
// speedup vs baseline: 1.4181x; 1.4181x over previous
#include <cuda_runtime.h>
#include <cuda_fp16.h>
#include <cstdint>

typedef __half fp16;

#define Bx 4
#define Sx 2048
#define Hx 1024
#define Mx 8192            // B*S
#define CH 32              // scan chunk length
#define NCH 64             // S / CH

// ---------------- device scratch ----------------
__device__ __align__(256) fp16  g_Xhi[Mx * Hx];
__device__ __align__(256) fp16  g_Xlo[Mx * Hx];
__device__ __align__(256) fp16  g_Whi[3 * Hx * Hx];   // [Wi, Wf, Wg] fp16
__device__ __align__(256) fp16  g_Wohi[Hx * Hx];
__device__ __align__(256) float g_Yi[Mx * Hx];        // i_raw -> local h (in place)
__device__ __align__(256) float g_Yf[Mx * Hx];        // f_raw -> cumprod (in place)
__device__ __align__(256) float g_Yg[Mx * Hx];        // g (raw)
__device__ __align__(256) fp16  g_GHhi[Mx * Hx];
__device__ __align__(256) fp16  g_GHlo[Mx * Hx];
__device__ float g_P[Bx * NCH * Hx];
__device__ float g_E[Bx * NCH * Hx];
__device__ float g_Cr[Bx * NCH * Hx];

// ---------------- PTX helpers ----------------
__device__ __forceinline__ uint32_t smem_u32(const void* p) {
    uint32_t a;
    asm("{ .reg .u64 t; cvta.to.shared.u64 t, %1; cvt.u32.u64 %0, t; }" : "=r"(a) : "l"(p));
    return a;
}

__device__ __forceinline__ void ldsm_x4(uint32_t& r0, uint32_t& r1, uint32_t& r2,
                                        uint32_t& r3, uint32_t addr) {
    asm volatile("ldmatrix.sync.aligned.m8n8.x4.shared.b16 {%0,%1,%2,%3}, [%4];"
                 : "=r"(r0), "=r"(r1), "=r"(r2), "=r"(r3) : "r"(addr));
}

__device__ __forceinline__ void mma_fp16(float* c, const uint32_t* a, const uint32_t* b) {
    asm volatile(
        "mma.sync.aligned.m16n8k16.row.col.f32.f16.f16.f32 "
        "{%0,%1,%2,%3}, {%4,%5,%6,%7}, {%8,%9}, {%0,%1,%2,%3};"
        : "+f"(c[0]), "+f"(c[1]), "+f"(c[2]), "+f"(c[3])
        : "r"(a[0]), "r"(a[1]), "r"(a[2]), "r"(a[3]), "r"(b[0]), "r"(b[1]));
}

// ---------------- GEMM: C[M,N] = A[M,K] @ W[N,K]^T, fp16x2-split(A), fp32 out
// CTA tile 128x128, K-chunk 64, 4-stage cp.async pipeline (loads 3 ahead),
// 8 warps (2x4), warp tile 64x32, fragment double-buffering.
#define STAGE_BYTES 49152u          // 3 tiles x (128 x 64 fp16) = 3 x 16KB
#define NSTAGE 4
#define GEMM_SMEM   (1024 + NSTAGE * 49152)

__device__ __forceinline__ void load_tile(uint32_t tb, const fp16* __restrict__ src,
                                          int row0, int k0, int tid) {
    const char* gbase = (const char*)(src + (size_t)row0 * Hx + k0);
#pragma unroll
    for (int i = 0; i < 4; i++) {
        int gid = tid + i * 256;        // 1024 granules of 16B
        int row = gid >> 3;
        int g   = gid & 7;
        const char* gp = gbase + (size_t)row * (Hx * 2) + g * 16;
        uint32_t sp = tb + (uint32_t)(row * 128) + (uint32_t)((g ^ (row & 7)) << 4);
        asm volatile("cp.async.cg.shared.global [%0], [%1], 16;"
                     :: "r"(sp), "l"(gp) : "memory");
    }
}

__global__ void __launch_bounds__(256, 1) k_gemm(
    const fp16* __restrict__ Ah, const fp16* __restrict__ Al,
    const fp16* __restrict__ Bh_,
    float* __restrict__ C0, float* __restrict__ C1, float* __restrict__ C2,
    int zstride)
{
    extern __shared__ char smem_raw[];
    uint32_t sb     = smem_u32(smem_raw);
    uint32_t stage0 = (sb + 1023u) & ~1023u;

    const int tid = threadIdx.x;
    const int wid = tid >> 5;
    const int lid = tid & 31;
    const int wr  = wid >> 2;       // 0-1  -> m offset wr*64
    const int wc  = wid & 3;        // 0-3  -> n offset wc*32
    const int n0  = blockIdx.x * 128;
    const int m0  = blockIdx.y * 128;
    const int z   = blockIdx.z;
    const fp16* Bh = Bh_ + (size_t)z * zstride;
    float* C = (z == 0) ? C0 : ((z == 1) ? C1 : C2);

    // prologue: fill stages 0..2
#pragma unroll
    for (int s = 0; s < NSTAGE - 1; s++) {
        uint32_t st = stage0 + s * STAGE_BYTES;
        load_tile(st,          Ah, m0, s * 64, tid);
        load_tile(st + 16384u, Al, m0, s * 64, tid);
        load_tile(st + 32768u, Bh, n0, s * 64, tid);
        asm volatile("cp.async.commit_group;" ::: "memory");
    }

    float acc[4][4][4];
#pragma unroll
    for (int a = 0; a < 4; a++)
#pragma unroll
        for (int b = 0; b < 4; b++)
#pragma unroll
            for (int c = 0; c < 4; c++) acc[a][b][c] = 0.f;

    const int aRow = lid & 15;
    const int aCg  = lid >> 4;
    const int bRow = (lid & 7) | ((lid & 16) >> 1);
    const int bCg  = (lid >> 3) & 1;
    const uint32_t aSwz = (uint32_t)(aRow & 7);
    const uint32_t bSwz = (uint32_t)(bRow & 7);
    uint32_t aOff[4], bOff[2];
#pragma unroll
    for (int mt = 0; mt < 4; mt++) aOff[mt] = (uint32_t)((wr * 64 + mt * 16 + aRow) * 128);
#pragma unroll
    for (int nt = 0; nt < 2; nt++) bOff[nt] = (uint32_t)((wc * 32 + nt * 16 + bRow) * 128);

    uint32_t ah[2][4][4], al[2][4][4], bhf[2][2][4];

#define LOAD_FRAGS(buf, sbase, ks_) do {                                        \
    uint32_t soA = (uint32_t)(((2 * (ks_) + aCg) ^ aSwz) << 4);                 \
    uint32_t soB = (uint32_t)(((2 * (ks_) + bCg) ^ bSwz) << 4);                 \
    _Pragma("unroll")                                                           \
    for (int mt = 0; mt < 4; mt++) {                                            \
        uint32_t off = aOff[mt] + soA;                                          \
        ldsm_x4(ah[buf][mt][0], ah[buf][mt][1], ah[buf][mt][2], ah[buf][mt][3], \
                (sbase) + off);                                                 \
        ldsm_x4(al[buf][mt][0], al[buf][mt][1], al[buf][mt][2], al[buf][mt][3], \
                (sbase) + 16384u + off);                                        \
    }                                                                           \
    _Pragma("unroll")                                                           \
    for (int nt = 0; nt < 2; nt++) {                                            \
        uint32_t off = bOff[nt] + soB;                                          \
        ldsm_x4(bhf[buf][nt][0], bhf[buf][nt][1], bhf[buf][nt][2],              \
                bhf[buf][nt][3], (sbase) + 32768u + off);                       \
    }                                                                           \
} while (0)

#define COMPUTE(buf) do {                                                       \
    _Pragma("unroll")                                                           \
    for (int mt = 0; mt < 4; mt++)                                              \
        _Pragma("unroll")                                                       \
        for (int nt = 0; nt < 4; nt++) {                                        \
            const uint32_t* bh2 = &bhf[buf][nt >> 1][(nt & 1) * 2];             \
            mma_fp16(acc[mt][nt], ah[buf][mt], bh2);                            \
            mma_fp16(acc[mt][nt], al[buf][mt], bh2);                            \
        }                                                                       \
} while (0)

    for (int k = 0; k < 16; k++) {
        uint32_t sbase = stage0 + (uint32_t)(k % NSTAGE) * STAGE_BYTES;

        // last issued group at this point = min(15, k+2); keep group k complete
        if (k <= 13)      asm volatile("cp.async.wait_group 2;" ::: "memory");
        else if (k == 14) asm volatile("cp.async.wait_group 1;" ::: "memory");
        else              asm volatile("cp.async.wait_group 0;" ::: "memory");
        __syncthreads();   // all warps done with iter k-1 -> slot (k-1)%4 free

        // issue loads for stage k+3 into slot (k+3)%4 == (k-1)%4
        int kn = k + 3;
        if (kn < 16) {
            uint32_t lbase = stage0 + (uint32_t)(kn % NSTAGE) * STAGE_BYTES;
            load_tile(lbase,          Ah, m0, kn * 64, tid);
            load_tile(lbase + 16384u, Al, m0, kn * 64, tid);
            load_tile(lbase + 32768u, Bh, n0, kn * 64, tid);
            asm volatile("cp.async.commit_group;" ::: "memory");
        }

        LOAD_FRAGS(0, sbase, 0);
#pragma unroll
        for (int ks = 0; ks < 4; ks++) {
            int cur = ks & 1;
            if (ks < 3) LOAD_FRAGS((cur ^ 1), sbase, (ks + 1));
            COMPUTE(cur);
        }
    }

    // epilogue
    const int g4 = lid >> 2;
    const int t4 = lid & 3;
#pragma unroll
    for (int mt = 0; mt < 4; mt++) {
        int row = m0 + wr * 64 + mt * 16 + g4;
#pragma unroll
        for (int nt = 0; nt < 4; nt++) {
            int col = n0 + wc * 32 + nt * 8 + t4 * 2;
            float2 v0 = make_float2(acc[mt][nt][0], acc[mt][nt][1]);
            float2 v1 = make_float2(acc[mt][nt][2], acc[mt][nt][3]);
            *(float2*)(C + (size_t)row * Hx + col)       = v0;
            *(float2*)(C + (size_t)(row + 8) * Hx + col) = v1;
        }
    }
}

// ---------------- small kernels ----------------
__global__ void k_split(const float* __restrict__ src, fp16* __restrict__ hi,
                        fp16* __restrict__ lo, int n) {
    int i = blockIdx.x * blockDim.x + threadIdx.x;
    if (i < n) {
        float x = src[i];
        fp16 h = __float2half_rn(x);
        hi[i] = h;
        lo[i] = __float2half_rn(x - __half2float(h));
    }
}

// all 4 weight conversions (fp16, no split needed on W side)
__global__ void k_splitW(const float* __restrict__ Wi, const float* __restrict__ Wf,
                         const float* __restrict__ Wg, const float* __restrict__ Wo) {
    int i = blockIdx.x * blockDim.x + threadIdx.x;
    int y = blockIdx.y;
    const float* s = (y == 0) ? Wi : (y == 1) ? Wf : (y == 2) ? Wg : Wo;
    fp16* hi = (y < 3) ? (g_Whi + (size_t)y * (Hx * Hx)) : g_Wohi;
    hi[i] = __float2half_rn(s[i]);
}

// pass 1: activation + chunk-local scan fused, batch-of-4 load grouping.
__global__ void k_scan1() {
    int tid = blockIdx.x * blockDim.x + threadIdx.x;   // B*NCH*H = 262144
    int h  = tid & (Hx - 1);
    int bc = tid >> 10;          // b*NCH + c
    int b  = bc >> 6;
    int c  = bc & (NCH - 1);
    size_t base = ((size_t)(b * Sx + c * CH)) * Hx + h;
    float p = 1.f, hl = 0.f;
    for (int tb = 0; tb < CH; tb += 4) {
        float fr[4], ir[4];
#pragma unroll
        for (int j = 0; j < 4; j++) {
            size_t idx = base + (size_t)(tb + j) * Hx;
            fr[j] = g_Yf[idx];
            ir[j] = g_Yi[idx];
        }
#pragma unroll
        for (int j = 0; j < 4; j++) {
            float f  = 1.f / (1.f + __expf(-fr[j]));
            float s  = 1.f / (1.f + __expf(-ir[j]));
            float in = ir[j] * s * (1.f - f);
            hl = f * hl + in;
            p  = p * f;
            fr[j] = p;
            ir[j] = hl;
        }
#pragma unroll
        for (int j = 0; j < 4; j++) {
            size_t idx = base + (size_t)(tb + j) * Hx;
            g_Yf[idx] = fr[j];
            g_Yi[idx] = ir[j];
        }
    }
    g_P[tid] = p;
    g_E[tid] = hl;
}

// pass 2: scan across chunks per channel
__global__ void k_scan2() {
    int tid = blockIdx.x * blockDim.x + threadIdx.x;   // B*H = 4096
    int h = tid & (Hx - 1);
    int b = tid >> 10;
    float carry = 0.f;
#pragma unroll
    for (int c = 0; c < NCH; c++) {
        int idx = ((b * NCH + c) << 10) + h;
        g_Cr[idx] = carry;
        carry = g_P[idx] * carry + g_E[idx];
    }
}

// pass 3: h = h_local + cumprod(f)*carry; gh = g*h; fp16 hi/lo split
__global__ void k_scan3(int n) {
    int i = blockIdx.x * blockDim.x + threadIdx.x;
    if (i < n) {
        int h = i & (Hx - 1);
        int s = (i >> 10) & (Sx - 1);
        int b = i >> 21;
        int c = s >> 5;                 // CH = 32
        float carry = g_Cr[((b * NCH + c) << 10) + h];
        float hv = g_Yi[i] + g_Yf[i] * carry;
        float gh = g_Yg[i] * hv;
        fp16 hi = __float2half_rn(gh);
        g_GHhi[i] = hi;
        g_GHlo[i] = __float2half_rn(gh - __half2float(hi));
    }
}

// ---------------- launch ----------------
extern "C" void kernel_launch(void* const* d_in, const int* in_sizes, int n_in,
                              void* d_out, int out_size) {
    const float* x  = (const float*)d_in[0];
    const float* Wi = (const float*)d_in[1];
    const float* Wf = (const float*)d_in[2];
    const float* Wg = (const float*)d_in[3];
    const float* Wo = (const float*)d_in[4];
    float* out = (float*)d_out;

    cudaFuncSetAttribute(k_gemm, cudaFuncAttributeMaxDynamicSharedMemorySize, GEMM_SMEM);

    fp16 *Xhi, *Xlo, *Whi, *Wohi, *GHhi, *GHlo;
    float *Yi, *Yf, *Yg;
    cudaGetSymbolAddress((void**)&Xhi,  g_Xhi);
    cudaGetSymbolAddress((void**)&Xlo,  g_Xlo);
    cudaGetSymbolAddress((void**)&Whi,  g_Whi);
    cudaGetSymbolAddress((void**)&Wohi, g_Wohi);
    cudaGetSymbolAddress((void**)&GHhi, g_GHhi);
    cudaGetSymbolAddress((void**)&GHlo, g_GHlo);
    cudaGetSymbolAddress((void**)&Yi,   g_Yi);
    cudaGetSymbolAddress((void**)&Yf,   g_Yf);
    cudaGetSymbolAddress((void**)&Yg,   g_Yg);

    const int NE = Mx * Hx;     // 8388608
    const int NW = Hx * Hx;     // 1048576

    k_split<<<NE / 256, 256>>>(x, Xhi, Xlo, NE);
    dim3 gw(NW / 256, 4);
    k_splitW<<<gw, 256>>>(Wi, Wf, Wg, Wo);

    // GEMM1: Yi = x@Wi^T, Yf = x@Wf^T, Yg = x@Wg^T (z-fused)
    dim3 g1(Hx / 128, Mx / 128, 3);
    k_gemm<<<g1, 256, GEMM_SMEM>>>(Xhi, Xlo, Whi, Yi, Yf, Yg, NW);

    // act + chunked linear recurrence
    k_scan1<<<(Bx * NCH * Hx) / 256, 256>>>();
    k_scan2<<<(Bx * Hx) / 256, 256>>>();
    k_scan3<<<NE / 256, 256>>>(NE);

    // GEMM2: out = (g*h) @ Wo^T
    dim3 g2(Hx / 128, Mx / 128, 1);
    k_gemm<<<g2, 256, GEMM_SMEM>>>(GHhi, GHlo, Wohi, out, out, out, 0);
}

// round 5
// speedup vs baseline: 2.0175x; 1.4227x over previous
#include <cuda_runtime.h>
#include <cuda_fp16.h>
#include <cstdint>

typedef __half fp16;

#define Bx 4
#define Sx 2048
#define Hx 1024
#define Mx 8192            // B*S
#define CH 32              // scan chunk length
#define NCH 64             // S / CH

// ---------------- device scratch ----------------
__device__ __align__(256) fp16  g_Xh[Mx * Hx];
__device__ __align__(256) fp16  g_Wh[3 * Hx * Hx];    // [Wi, Wf, Wg] fp16
__device__ __align__(256) fp16  g_Woh[Hx * Hx];
__device__ __align__(256) float g_Yi[Mx * Hx];        // i_raw -> local h (in place)
__device__ __align__(256) float g_Yf[Mx * Hx];        // f_raw -> cumprod (in place)
__device__ __align__(256) float g_Yg[Mx * Hx];        // g (raw)
__device__ __align__(256) fp16  g_GH[Mx * Hx];
__device__ float g_P[Bx * NCH * Hx];
__device__ float g_E[Bx * NCH * Hx];
__device__ float g_Cr[Bx * NCH * Hx];

// ---------------- PTX helpers ----------------
__device__ __forceinline__ uint32_t smem_u32(const void* p) {
    uint32_t a;
    asm("{ .reg .u64 t; cvta.to.shared.u64 t, %1; cvt.u32.u64 %0, t; }" : "=r"(a) : "l"(p));
    return a;
}

__device__ __forceinline__ void ldsm_x4(uint32_t& r0, uint32_t& r1, uint32_t& r2,
                                        uint32_t& r3, uint32_t addr) {
    asm volatile("ldmatrix.sync.aligned.m8n8.x4.shared.b16 {%0,%1,%2,%3}, [%4];"
                 : "=r"(r0), "=r"(r1), "=r"(r2), "=r"(r3) : "r"(addr));
}

__device__ __forceinline__ void mma_fp16(float* c, const uint32_t* a, const uint32_t* b) {
    asm volatile(
        "mma.sync.aligned.m16n8k16.row.col.f32.f16.f16.f32 "
        "{%0,%1,%2,%3}, {%4,%5,%6,%7}, {%8,%9}, {%0,%1,%2,%3};"
        : "+f"(c[0]), "+f"(c[1]), "+f"(c[2]), "+f"(c[3])
        : "r"(a[0]), "r"(a[1]), "r"(a[2]), "r"(a[3]), "r"(b[0]), "r"(b[1]));
}

// ---------------- GEMM: C[M,N] = A[M,K] @ W[N,K]^T, fp16, fp32 accum -------
// CTA tile 128x128, K-chunk 64, 4-stage cp.async pipeline (loads 3 ahead),
// 8 warps (2x4), warp tile 64x32, fragment double-buffering.
#define STAGE_BYTES 32768u          // 2 tiles x (128 x 64 fp16) = 2 x 16KB
#define NSTAGE 4
#define GEMM_SMEM   (1024 + NSTAGE * 32768)

__device__ __forceinline__ void load_tile(uint32_t tb, const fp16* __restrict__ src,
                                          int row0, int k0, int tid) {
    const char* gbase = (const char*)(src + (size_t)row0 * Hx + k0);
#pragma unroll
    for (int i = 0; i < 4; i++) {
        int gid = tid + i * 256;        // 1024 granules of 16B
        int row = gid >> 3;
        int g   = gid & 7;
        const char* gp = gbase + (size_t)row * (Hx * 2) + g * 16;
        uint32_t sp = tb + (uint32_t)(row * 128) + (uint32_t)((g ^ (row & 7)) << 4);
        asm volatile("cp.async.cg.shared.global [%0], [%1], 16;"
                     :: "r"(sp), "l"(gp) : "memory");
    }
}

__global__ void __launch_bounds__(256, 1) k_gemm(
    const fp16* __restrict__ Ah,
    const fp16* __restrict__ Bh_,
    float* __restrict__ C0, float* __restrict__ C1, float* __restrict__ C2,
    int zstride)
{
    extern __shared__ char smem_raw[];
    uint32_t sb     = smem_u32(smem_raw);
    uint32_t stage0 = (sb + 1023u) & ~1023u;

    const int tid = threadIdx.x;
    const int wid = tid >> 5;
    const int lid = tid & 31;
    const int wr  = wid >> 2;       // 0-1  -> m offset wr*64
    const int wc  = wid & 3;        // 0-3  -> n offset wc*32
    const int n0  = blockIdx.x * 128;
    const int m0  = blockIdx.y * 128;
    const int z   = blockIdx.z;
    const fp16* Bh = Bh_ + (size_t)z * zstride;
    float* C = (z == 0) ? C0 : ((z == 1) ? C1 : C2);

    // prologue: fill stages 0..2
#pragma unroll
    for (int s = 0; s < NSTAGE - 1; s++) {
        uint32_t st = stage0 + s * STAGE_BYTES;
        load_tile(st,          Ah, m0, s * 64, tid);
        load_tile(st + 16384u, Bh, n0, s * 64, tid);
        asm volatile("cp.async.commit_group;" ::: "memory");
    }

    float acc[4][4][4];
#pragma unroll
    for (int a = 0; a < 4; a++)
#pragma unroll
        for (int b = 0; b < 4; b++)
#pragma unroll
            for (int c = 0; c < 4; c++) acc[a][b][c] = 0.f;

    const int aRow = lid & 15;
    const int aCg  = lid >> 4;
    const int bRow = (lid & 7) | ((lid & 16) >> 1);
    const int bCg  = (lid >> 3) & 1;
    const uint32_t aSwz = (uint32_t)(aRow & 7);
    const uint32_t bSwz = (uint32_t)(bRow & 7);
    uint32_t aOff[4], bOff[2];
#pragma unroll
    for (int mt = 0; mt < 4; mt++) aOff[mt] = (uint32_t)((wr * 64 + mt * 16 + aRow) * 128);
#pragma unroll
    for (int nt = 0; nt < 2; nt++) bOff[nt] = (uint32_t)((wc * 32 + nt * 16 + bRow) * 128);

    uint32_t ah[2][4][4], bhf[2][2][4];

#define LOAD_FRAGS(buf, sbase, ks_) do {                                        \
    uint32_t soA = (uint32_t)(((2 * (ks_) + aCg) ^ aSwz) << 4);                 \
    uint32_t soB = (uint32_t)(((2 * (ks_) + bCg) ^ bSwz) << 4);                 \
    _Pragma("unroll")                                                           \
    for (int mt = 0; mt < 4; mt++) {                                            \
        ldsm_x4(ah[buf][mt][0], ah[buf][mt][1], ah[buf][mt][2], ah[buf][mt][3], \
                (sbase) + aOff[mt] + soA);                                      \
    }                                                                           \
    _Pragma("unroll")                                                           \
    for (int nt = 0; nt < 2; nt++) {                                            \
        ldsm_x4(bhf[buf][nt][0], bhf[buf][nt][1], bhf[buf][nt][2],              \
                bhf[buf][nt][3], (sbase) + 16384u + bOff[nt] + soB);            \
    }                                                                           \
} while (0)

#define COMPUTE(buf) do {                                                       \
    _Pragma("unroll")                                                           \
    for (int mt = 0; mt < 4; mt++)                                              \
        _Pragma("unroll")                                                       \
        for (int nt = 0; nt < 4; nt++) {                                        \
            const uint32_t* bh2 = &bhf[buf][nt >> 1][(nt & 1) * 2];             \
            mma_fp16(acc[mt][nt], ah[buf][mt], bh2);                            \
        }                                                                       \
} while (0)

    for (int k = 0; k < 16; k++) {
        uint32_t sbase = stage0 + (uint32_t)(k % NSTAGE) * STAGE_BYTES;

        if (k <= 13)      asm volatile("cp.async.wait_group 2;" ::: "memory");
        else if (k == 14) asm volatile("cp.async.wait_group 1;" ::: "memory");
        else              asm volatile("cp.async.wait_group 0;" ::: "memory");
        __syncthreads();   // all warps done with iter k-1 -> slot (k-1)%4 free

        int kn = k + 3;
        if (kn < 16) {
            uint32_t lbase = stage0 + (uint32_t)(kn % NSTAGE) * STAGE_BYTES;
            load_tile(lbase,          Ah, m0, kn * 64, tid);
            load_tile(lbase + 16384u, Bh, n0, kn * 64, tid);
            asm volatile("cp.async.commit_group;" ::: "memory");
        }

        LOAD_FRAGS(0, sbase, 0);
#pragma unroll
        for (int ks = 0; ks < 4; ks++) {
            int cur = ks & 1;
            if (ks < 3) LOAD_FRAGS((cur ^ 1), sbase, (ks + 1));
            COMPUTE(cur);
        }
    }

    // epilogue
    const int g4 = lid >> 2;
    const int t4 = lid & 3;
#pragma unroll
    for (int mt = 0; mt < 4; mt++) {
        int row = m0 + wr * 64 + mt * 16 + g4;
#pragma unroll
        for (int nt = 0; nt < 4; nt++) {
            int col = n0 + wc * 32 + nt * 8 + t4 * 2;
            float2 v0 = make_float2(acc[mt][nt][0], acc[mt][nt][1]);
            float2 v1 = make_float2(acc[mt][nt][2], acc[mt][nt][3]);
            *(float2*)(C + (size_t)row * Hx + col)       = v0;
            *(float2*)(C + (size_t)(row + 8) * Hx + col) = v1;
        }
    }
}

// ---------------- small kernels ----------------
__global__ void k_cvt(const float* __restrict__ src, fp16* __restrict__ dst, int n) {
    int i = blockIdx.x * blockDim.x + threadIdx.x;
    if (i < n) dst[i] = __float2half_rn(src[i]);
}

__global__ void k_cvtW(const float* __restrict__ Wi, const float* __restrict__ Wf,
                       const float* __restrict__ Wg, const float* __restrict__ Wo) {
    int i = blockIdx.x * blockDim.x + threadIdx.x;
    int y = blockIdx.y;
    const float* s = (y == 0) ? Wi : (y == 1) ? Wf : (y == 2) ? Wg : Wo;
    fp16* d = (y < 3) ? (g_Wh + (size_t)y * (Hx * Hx)) : g_Woh;
    d[i] = __float2half_rn(s[i]);
}

// pass 1: activation + chunk-local scan fused, batch-of-4 load grouping.
__global__ void k_scan1() {
    int tid = blockIdx.x * blockDim.x + threadIdx.x;   // B*NCH*H = 262144
    int h  = tid & (Hx - 1);
    int bc = tid >> 10;          // b*NCH + c
    int b  = bc >> 6;
    int c  = bc & (NCH - 1);
    size_t base = ((size_t)(b * Sx + c * CH)) * Hx + h;
    float p = 1.f, hl = 0.f;
    for (int tb = 0; tb < CH; tb += 4) {
        float fr[4], ir[4];
#pragma unroll
        for (int j = 0; j < 4; j++) {
            size_t idx = base + (size_t)(tb + j) * Hx;
            fr[j] = g_Yf[idx];
            ir[j] = g_Yi[idx];
        }
#pragma unroll
        for (int j = 0; j < 4; j++) {
            float f  = 1.f / (1.f + __expf(-fr[j]));
            float s  = 1.f / (1.f + __expf(-ir[j]));
            float in = ir[j] * s * (1.f - f);
            hl = f * hl + in;
            p  = p * f;
            fr[j] = p;
            ir[j] = hl;
        }
#pragma unroll
        for (int j = 0; j < 4; j++) {
            size_t idx = base + (size_t)(tb + j) * Hx;
            g_Yf[idx] = fr[j];
            g_Yi[idx] = ir[j];
        }
    }
    g_P[tid] = p;
    g_E[tid] = hl;
}

// pass 2: scan across chunks per channel
__global__ void k_scan2() {
    int tid = blockIdx.x * blockDim.x + threadIdx.x;   // B*H = 4096
    int h = tid & (Hx - 1);
    int b = tid >> 10;
    float carry = 0.f;
#pragma unroll
    for (int c = 0; c < NCH; c++) {
        int idx = ((b * NCH + c) << 10) + h;
        g_Cr[idx] = carry;
        carry = g_P[idx] * carry + g_E[idx];
    }
}

// pass 3: h = h_local + cumprod(f)*carry; gh = g*h; fp16
__global__ void k_scan3(int n) {
    int i = blockIdx.x * blockDim.x + threadIdx.x;
    if (i < n) {
        int h = i & (Hx - 1);
        int s = (i >> 10) & (Sx - 1);
        int b = i >> 21;
        int c = s >> 5;                 // CH = 32
        float carry = g_Cr[((b * NCH + c) << 10) + h];
        float hv = g_Yi[i] + g_Yf[i] * carry;
        g_GH[i] = __float2half_rn(g_Yg[i] * hv);
    }
}

// ---------------- launch ----------------
extern "C" void kernel_launch(void* const* d_in, const int* in_sizes, int n_in,
                              void* d_out, int out_size) {
    const float* x  = (const float*)d_in[0];
    const float* Wi = (const float*)d_in[1];
    const float* Wf = (const float*)d_in[2];
    const float* Wg = (const float*)d_in[3];
    const float* Wo = (const float*)d_in[4];
    float* out = (float*)d_out;

    cudaFuncSetAttribute(k_gemm, cudaFuncAttributeMaxDynamicSharedMemorySize, GEMM_SMEM);

    fp16 *Xh, *Wh, *Woh, *GH;
    float *Yi, *Yf, *Yg;
    cudaGetSymbolAddress((void**)&Xh,  g_Xh);
    cudaGetSymbolAddress((void**)&Wh,  g_Wh);
    cudaGetSymbolAddress((void**)&Woh, g_Woh);
    cudaGetSymbolAddress((void**)&GH,  g_GH);
    cudaGetSymbolAddress((void**)&Yi,  g_Yi);
    cudaGetSymbolAddress((void**)&Yf,  g_Yf);
    cudaGetSymbolAddress((void**)&Yg,  g_Yg);

    const int NE = Mx * Hx;     // 8388608
    const int NW = Hx * Hx;     // 1048576

    k_cvt<<<NE / 256, 256>>>(x, Xh, NE);
    dim3 gw(NW / 256, 4);
    k_cvtW<<<gw, 256>>>(Wi, Wf, Wg, Wo);

    // GEMM1: Yi = x@Wi^T, Yf = x@Wf^T, Yg = x@Wg^T (z-fused)
    dim3 g1(Hx / 128, Mx / 128, 3);
    k_gemm<<<g1, 256, GEMM_SMEM>>>(Xh, Wh, Yi, Yf, Yg, NW);

    // act + chunked linear recurrence
    k_scan1<<<(Bx * NCH * Hx) / 256, 256>>>();
    k_scan2<<<(Bx * Hx) / 256, 256>>>();
    k_scan3<<<NE / 256, 256>>>(NE);

    // GEMM2: out = (g*h) @ Wo^T
    dim3 g2(Hx / 128, Mx / 128, 1);
    k_gemm<<<g2, 256, GEMM_SMEM>>>(GH, Woh, out, out, out, 0);
}

// round 6
// speedup vs baseline: 2.3042x; 1.1421x over previous
#include <cuda_runtime.h>
#include <cuda_fp16.h>
#include <cstdint>

typedef __half fp16;

#define Bx 4
#define Sx 2048
#define Hx 1024
#define Mx 8192            // B*S
#define CH 32              // scan chunk length
#define NCH 64             // S / CH

// ---------------- device scratch ----------------
__device__ __align__(256) fp16  g_Xh[Mx * Hx];
__device__ __align__(256) fp16  g_Wh[3 * Hx * Hx];    // [Wi, Wf, Wg] fp16
__device__ __align__(256) fp16  g_Woh[Hx * Hx];
__device__ __align__(256) fp16  g_Yi[Mx * Hx];        // i_raw (fp16)
__device__ __align__(256) fp16  g_Yf[Mx * Hx];        // f_raw (fp16)
__device__ __align__(256) fp16  g_Yg[Mx * Hx];        // g raw (fp16)
__device__ __align__(256) fp16  g_Pc[Mx * Hx];        // chunk-local cumprod(f)
__device__ __align__(256) fp16  g_Hl[Mx * Hx];        // chunk-local h
__device__ __align__(256) fp16  g_GH[Mx * Hx];
__device__ float g_P[Bx * NCH * Hx];
__device__ float g_E[Bx * NCH * Hx];
__device__ float g_Cr[Bx * NCH * Hx];

// ---------------- PTX helpers ----------------
__device__ __forceinline__ uint32_t smem_u32(const void* p) {
    uint32_t a;
    asm("{ .reg .u64 t; cvta.to.shared.u64 t, %1; cvt.u32.u64 %0, t; }" : "=r"(a) : "l"(p));
    return a;
}

__device__ __forceinline__ void ldsm_x4(uint32_t& r0, uint32_t& r1, uint32_t& r2,
                                        uint32_t& r3, uint32_t addr) {
    asm volatile("ldmatrix.sync.aligned.m8n8.x4.shared.b16 {%0,%1,%2,%3}, [%4];"
                 : "=r"(r0), "=r"(r1), "=r"(r2), "=r"(r3) : "r"(addr));
}

__device__ __forceinline__ void mma_fp16(float* c, const uint32_t* a, const uint32_t* b) {
    asm volatile(
        "mma.sync.aligned.m16n8k16.row.col.f32.f16.f16.f32 "
        "{%0,%1,%2,%3}, {%4,%5,%6,%7}, {%8,%9}, {%0,%1,%2,%3};"
        : "+f"(c[0]), "+f"(c[1]), "+f"(c[2]), "+f"(c[3])
        : "r"(a[0]), "r"(a[1]), "r"(a[2]), "r"(a[3]), "r"(b[0]), "r"(b[1]));
}

// ---------------- GEMM: C[M,N] = A[M,K] @ W[N,K]^T, fp16, fp32 accum -------
// CTA tile 128x128, K-chunk 64, 3-stage cp.async pipeline (loads 2 ahead),
// 8 warps (2x4), warp tile 64x32, frag double-buffer, 2 CTAs/SM.
#define STAGE_BYTES 32768u          // 2 tiles x (128 x 64 fp16)
#define NSTAGE 3
#define GEMM_SMEM   (1024 + NSTAGE * 32768)

__device__ __forceinline__ void load_tile(uint32_t tb, const fp16* __restrict__ src,
                                          int row0, int k0, int tid) {
    const char* gbase = (const char*)(src + (size_t)row0 * Hx + k0);
#pragma unroll
    for (int i = 0; i < 4; i++) {
        int gid = tid + i * 256;        // 1024 granules of 16B
        int row = gid >> 3;
        int g   = gid & 7;
        const char* gp = gbase + (size_t)row * (Hx * 2) + g * 16;
        uint32_t sp = tb + (uint32_t)(row * 128) + (uint32_t)((g ^ (row & 7)) << 4);
        asm volatile("cp.async.cg.shared.global [%0], [%1], 16;"
                     :: "r"(sp), "l"(gp) : "memory");
    }
}

template <typename OutT>
__global__ void __launch_bounds__(256, 2) k_gemm(
    const fp16* __restrict__ Ah,
    const fp16* __restrict__ Bh_,
    OutT* __restrict__ C0, OutT* __restrict__ C1, OutT* __restrict__ C2,
    int zstride)
{
    extern __shared__ char smem_raw[];
    uint32_t sb     = smem_u32(smem_raw);
    uint32_t stage0 = (sb + 1023u) & ~1023u;

    const int tid = threadIdx.x;
    const int wid = tid >> 5;
    const int lid = tid & 31;
    const int wr  = wid >> 2;       // 0-1  -> m offset wr*64
    const int wc  = wid & 3;        // 0-3  -> n offset wc*32
    const int n0  = blockIdx.x * 128;
    const int m0  = blockIdx.y * 128;
    const int z   = blockIdx.z;
    const fp16* Bh = Bh_ + (size_t)z * zstride;
    OutT* C = (z == 0) ? C0 : ((z == 1) ? C1 : C2);

    // prologue: fill stages 0,1
#pragma unroll
    for (int s = 0; s < NSTAGE - 1; s++) {
        uint32_t st = stage0 + s * STAGE_BYTES;
        load_tile(st,          Ah, m0, s * 64, tid);
        load_tile(st + 16384u, Bh, n0, s * 64, tid);
        asm volatile("cp.async.commit_group;" ::: "memory");
    }

    float acc[4][4][4];
#pragma unroll
    for (int a = 0; a < 4; a++)
#pragma unroll
        for (int b = 0; b < 4; b++)
#pragma unroll
            for (int c = 0; c < 4; c++) acc[a][b][c] = 0.f;

    const int aRow = lid & 15;
    const int aCg  = lid >> 4;
    const int bRow = (lid & 7) | ((lid & 16) >> 1);
    const int bCg  = (lid >> 3) & 1;
    const uint32_t aSwz = (uint32_t)(aRow & 7);
    const uint32_t bSwz = (uint32_t)(bRow & 7);
    uint32_t aOff[4], bOff[2];
#pragma unroll
    for (int mt = 0; mt < 4; mt++) aOff[mt] = (uint32_t)((wr * 64 + mt * 16 + aRow) * 128);
#pragma unroll
    for (int nt = 0; nt < 2; nt++) bOff[nt] = (uint32_t)((wc * 32 + nt * 16 + bRow) * 128);

    uint32_t ah[2][4][4], bhf[2][2][4];

#define LOAD_FRAGS(buf, sbase, ks_) do {                                        \
    uint32_t soA = (uint32_t)(((2 * (ks_) + aCg) ^ aSwz) << 4);                 \
    uint32_t soB = (uint32_t)(((2 * (ks_) + bCg) ^ bSwz) << 4);                 \
    _Pragma("unroll")                                                           \
    for (int mt = 0; mt < 4; mt++) {                                            \
        ldsm_x4(ah[buf][mt][0], ah[buf][mt][1], ah[buf][mt][2], ah[buf][mt][3], \
                (sbase) + aOff[mt] + soA);                                      \
    }                                                                           \
    _Pragma("unroll")                                                           \
    for (int nt = 0; nt < 2; nt++) {                                            \
        ldsm_x4(bhf[buf][nt][0], bhf[buf][nt][1], bhf[buf][nt][2],              \
                bhf[buf][nt][3], (sbase) + 16384u + bOff[nt] + soB);            \
    }                                                                           \
} while (0)

#define COMPUTE(buf) do {                                                       \
    _Pragma("unroll")                                                           \
    for (int mt = 0; mt < 4; mt++)                                              \
        _Pragma("unroll")                                                       \
        for (int nt = 0; nt < 4; nt++) {                                        \
            const uint32_t* bh2 = &bhf[buf][nt >> 1][(nt & 1) * 2];             \
            mma_fp16(acc[mt][nt], ah[buf][mt], bh2);                            \
        }                                                                       \
} while (0)

    for (int k = 0; k < 16; k++) {
        uint32_t sbase = stage0 + (uint32_t)(k % NSTAGE) * STAGE_BYTES;

        if (k <= 14) asm volatile("cp.async.wait_group 1;" ::: "memory");
        else         asm volatile("cp.async.wait_group 0;" ::: "memory");
        __syncthreads();   // all warps done with iter k-1 -> slot (k-1)%3 free

        // issue loads for stage k+2 into slot (k+2)%3 == (k-1)%3
        int kn = k + 2;
        if (kn < 16) {
            uint32_t lbase = stage0 + (uint32_t)(kn % NSTAGE) * STAGE_BYTES;
            load_tile(lbase,          Ah, m0, kn * 64, tid);
            load_tile(lbase + 16384u, Bh, n0, kn * 64, tid);
            asm volatile("cp.async.commit_group;" ::: "memory");
        }

        LOAD_FRAGS(0, sbase, 0);
#pragma unroll
        for (int ks = 0; ks < 4; ks++) {
            int cur = ks & 1;
            if (ks < 3) LOAD_FRAGS((cur ^ 1), sbase, (ks + 1));
            COMPUTE(cur);
        }
    }

    // epilogue
    const int g4 = lid >> 2;
    const int t4 = lid & 3;
#pragma unroll
    for (int mt = 0; mt < 4; mt++) {
        int row = m0 + wr * 64 + mt * 16 + g4;
#pragma unroll
        for (int nt = 0; nt < 4; nt++) {
            int col = n0 + wc * 32 + nt * 8 + t4 * 2;
            if constexpr (sizeof(OutT) == 2) {
                *(__half2*)((fp16*)C + (size_t)row * Hx + col) =
                    __floats2half2_rn(acc[mt][nt][0], acc[mt][nt][1]);
                *(__half2*)((fp16*)C + (size_t)(row + 8) * Hx + col) =
                    __floats2half2_rn(acc[mt][nt][2], acc[mt][nt][3]);
            } else {
                *(float2*)((float*)C + (size_t)row * Hx + col) =
                    make_float2(acc[mt][nt][0], acc[mt][nt][1]);
                *(float2*)((float*)C + (size_t)(row + 8) * Hx + col) =
                    make_float2(acc[mt][nt][2], acc[mt][nt][3]);
            }
        }
    }
}

// ---------------- small kernels ----------------
__global__ void k_cvt(const float* __restrict__ src, fp16* __restrict__ dst, int n) {
    int i = blockIdx.x * blockDim.x + threadIdx.x;
    if (i < n) dst[i] = __float2half_rn(src[i]);
}

__global__ void k_cvtW(const float* __restrict__ Wi, const float* __restrict__ Wf,
                       const float* __restrict__ Wg, const float* __restrict__ Wo) {
    int i = blockIdx.x * blockDim.x + threadIdx.x;
    int y = blockIdx.y;
    const float* s = (y == 0) ? Wi : (y == 1) ? Wf : (y == 2) ? Wg : Wo;
    fp16* d = (y < 3) ? (g_Wh + (size_t)y * (Hx * Hx)) : g_Woh;
    d[i] = __float2half_rn(s[i]);
}

// pass 1: activation + chunk-local scan fused; fp16 in, fp16 out,
// fp32 chunk summaries.
__global__ void k_scan1() {
    int tid = blockIdx.x * blockDim.x + threadIdx.x;   // B*NCH*H = 262144
    int h  = tid & (Hx - 1);
    int bc = tid >> 10;          // b*NCH + c
    int b  = bc >> 6;
    int c  = bc & (NCH - 1);
    size_t base = ((size_t)(b * Sx + c * CH)) * Hx + h;
    float p = 1.f, hl = 0.f;
    for (int tb = 0; tb < CH; tb += 4) {
        float fr[4], ir[4];
#pragma unroll
        for (int j = 0; j < 4; j++) {
            size_t idx = base + (size_t)(tb + j) * Hx;
            fr[j] = __half2float(g_Yf[idx]);
            ir[j] = __half2float(g_Yi[idx]);
        }
#pragma unroll
        for (int j = 0; j < 4; j++) {
            float f  = 1.f / (1.f + __expf(-fr[j]));
            float s  = 1.f / (1.f + __expf(-ir[j]));
            float in = ir[j] * s * (1.f - f);
            hl = f * hl + in;
            p  = p * f;
            fr[j] = p;
            ir[j] = hl;
        }
#pragma unroll
        for (int j = 0; j < 4; j++) {
            size_t idx = base + (size_t)(tb + j) * Hx;
            g_Pc[idx] = __float2half_rn(fr[j]);
            g_Hl[idx] = __float2half_rn(ir[j]);
        }
    }
    g_P[tid] = p;
    g_E[tid] = hl;
}

// pass 2: scan across chunks per channel (fp32)
__global__ void k_scan2() {
    int tid = blockIdx.x * blockDim.x + threadIdx.x;   // B*H = 4096
    int h = tid & (Hx - 1);
    int b = tid >> 10;
    float carry = 0.f;
#pragma unroll
    for (int c = 0; c < NCH; c++) {
        int idx = ((b * NCH + c) << 10) + h;
        g_Cr[idx] = carry;
        carry = g_P[idx] * carry + g_E[idx];
    }
}

// pass 3: h = h_local + cumprod(f)*carry; gh = g*h; fp16
__global__ void k_scan3(int n) {
    int i = blockIdx.x * blockDim.x + threadIdx.x;
    if (i < n) {
        int h = i & (Hx - 1);
        int s = (i >> 10) & (Sx - 1);
        int b = i >> 21;
        int c = s >> 5;                 // CH = 32
        float carry = g_Cr[((b * NCH + c) << 10) + h];
        float hv = __half2float(g_Hl[i]) + __half2float(g_Pc[i]) * carry;
        g_GH[i] = __float2half_rn(__half2float(g_Yg[i]) * hv);
    }
}

// ---------------- launch ----------------
extern "C" void kernel_launch(void* const* d_in, const int* in_sizes, int n_in,
                              void* d_out, int out_size) {
    const float* x  = (const float*)d_in[0];
    const float* Wi = (const float*)d_in[1];
    const float* Wf = (const float*)d_in[2];
    const float* Wg = (const float*)d_in[3];
    const float* Wo = (const float*)d_in[4];
    float* out = (float*)d_out;

    cudaFuncSetAttribute(k_gemm<fp16>,  cudaFuncAttributeMaxDynamicSharedMemorySize, GEMM_SMEM);
    cudaFuncSetAttribute(k_gemm<float>, cudaFuncAttributeMaxDynamicSharedMemorySize, GEMM_SMEM);

    fp16 *Xh, *Wh, *Woh, *GH, *Yi, *Yf, *Yg;
    cudaGetSymbolAddress((void**)&Xh,  g_Xh);
    cudaGetSymbolAddress((void**)&Wh,  g_Wh);
    cudaGetSymbolAddress((void**)&Woh, g_Woh);
    cudaGetSymbolAddress((void**)&GH,  g_GH);
    cudaGetSymbolAddress((void**)&Yi,  g_Yi);
    cudaGetSymbolAddress((void**)&Yf,  g_Yf);
    cudaGetSymbolAddress((void**)&Yg,  g_Yg);

    const int NE = Mx * Hx;     // 8388608
    const int NW = Hx * Hx;     // 1048576

    k_cvt<<<NE / 256, 256>>>(x, Xh, NE);
    dim3 gw(NW / 256, 4);
    k_cvtW<<<gw, 256>>>(Wi, Wf, Wg, Wo);

    // GEMM1: Yi = x@Wi^T, Yf = x@Wf^T, Yg = x@Wg^T (z-fused, fp16 out)
    dim3 g1(Hx / 128, Mx / 128, 3);
    k_gemm<fp16><<<g1, 256, GEMM_SMEM>>>(Xh, Wh, Yi, Yf, Yg, NW);

    // act + chunked linear recurrence
    k_scan1<<<(Bx * NCH * Hx) / 256, 256>>>();
    k_scan2<<<(Bx * Hx) / 256, 256>>>();
    k_scan3<<<NE / 256, 256>>>(NE);

    // GEMM2: out = (g*h) @ Wo^T (fp32 out)
    dim3 g2(Hx / 128, Mx / 128, 1);
    k_gemm<float><<<g2, 256, GEMM_SMEM>>>(GH, Woh, out, out, out, 0);
}

// round 7
// speedup vs baseline: 2.3315x; 1.0119x over previous
#include <cuda_runtime.h>
#include <cuda_fp16.h>
#include <cstdint>

typedef __half fp16;

#define Bx 4
#define Sx 2048
#define Hx 1024
#define Mx 8192            // B*S
#define CH 32              // scan chunk length
#define NCH 64             // S / CH

// ---------------- device scratch ----------------
__device__ __align__(256) fp16  g_Xh[Mx * Hx];
__device__ __align__(256) fp16  g_Wh[3 * Hx * Hx];    // [Wi, Wf, Wg] fp16
__device__ __align__(256) fp16  g_Woh[Hx * Hx];
__device__ __align__(256) fp16  g_Yi[Mx * Hx];        // silu(i_raw)   (fp16)
__device__ __align__(256) fp16  g_Yf[Mx * Hx];        // sigmoid(f_raw)(fp16)
__device__ __align__(256) fp16  g_Yg[Mx * Hx];        // g raw (fp16)
__device__ __align__(256) __half2 g_PH[Mx * Hx];      // {cumprod(f), h_local}
__device__ __align__(256) fp16  g_GH[Mx * Hx];
__device__ float g_P[Bx * NCH * Hx];
__device__ float g_E[Bx * NCH * Hx];
__device__ float g_Cr[Bx * NCH * Hx];

// ---------------- PTX helpers ----------------
__device__ __forceinline__ uint32_t smem_u32(const void* p) {
    uint32_t a;
    asm("{ .reg .u64 t; cvta.to.shared.u64 t, %1; cvt.u32.u64 %0, t; }" : "=r"(a) : "l"(p));
    return a;
}

__device__ __forceinline__ void ldsm_x4(uint32_t& r0, uint32_t& r1, uint32_t& r2,
                                        uint32_t& r3, uint32_t addr) {
    asm volatile("ldmatrix.sync.aligned.m8n8.x4.shared.b16 {%0,%1,%2,%3}, [%4];"
                 : "=r"(r0), "=r"(r1), "=r"(r2), "=r"(r3) : "r"(addr));
}

__device__ __forceinline__ void mma_fp16(float* c, const uint32_t* a, const uint32_t* b) {
    asm volatile(
        "mma.sync.aligned.m16n8k16.row.col.f32.f16.f16.f32 "
        "{%0,%1,%2,%3}, {%4,%5,%6,%7}, {%8,%9}, {%0,%1,%2,%3};"
        : "+f"(c[0]), "+f"(c[1]), "+f"(c[2]), "+f"(c[3])
        : "r"(a[0]), "r"(a[1]), "r"(a[2]), "r"(a[3]), "r"(b[0]), "r"(b[1]));
}

// epilogue transforms: mode 0 = silu, 1 = sigmoid, 2 = identity
__device__ __forceinline__ float ep_xform(float v, int mode) {
    if (mode == 0) return v / (1.f + __expf(-v));          // silu
    if (mode == 1) return 1.f / (1.f + __expf(-v));        // sigmoid
    return v;
}

// ---------------- GEMM: C[M,N] = A[M,K] @ W[N,K]^T, fp16, fp32 accum -------
// CTA tile 128x128, K-chunk 64, 3-stage cp.async pipeline (loads 2 ahead),
// 8 warps (2x4), warp tile 64x32, frag double-buffer, 2 CTAs/SM.
#define STAGE_BYTES 32768u          // 2 tiles x (128 x 64 fp16)
#define NSTAGE 3
#define GEMM_SMEM   (1024 + NSTAGE * 32768)

__device__ __forceinline__ void load_tile(uint32_t tb, const fp16* __restrict__ src,
                                          int row0, int k0, int tid) {
    const char* gbase = (const char*)(src + (size_t)row0 * Hx + k0);
#pragma unroll
    for (int i = 0; i < 4; i++) {
        int gid = tid + i * 256;        // 1024 granules of 16B
        int row = gid >> 3;
        int g   = gid & 7;
        const char* gp = gbase + (size_t)row * (Hx * 2) + g * 16;
        uint32_t sp = tb + (uint32_t)(row * 128) + (uint32_t)((g ^ (row & 7)) << 4);
        asm volatile("cp.async.cg.shared.global [%0], [%1], 16;"
                     :: "r"(sp), "l"(gp) : "memory");
    }
}

template <typename OutT, bool ACT>
__global__ void __launch_bounds__(256, 2) k_gemm(
    const fp16* __restrict__ Ah,
    const fp16* __restrict__ Bh_,
    OutT* __restrict__ C0, OutT* __restrict__ C1, OutT* __restrict__ C2,
    int zstride)
{
    extern __shared__ char smem_raw[];
    uint32_t sb     = smem_u32(smem_raw);
    uint32_t stage0 = (sb + 1023u) & ~1023u;

    const int tid = threadIdx.x;
    const int wid = tid >> 5;
    const int lid = tid & 31;
    const int wr  = wid >> 2;       // 0-1  -> m offset wr*64
    const int wc  = wid & 3;        // 0-3  -> n offset wc*32
    const int n0  = blockIdx.x * 128;
    const int m0  = blockIdx.y * 128;
    const int z   = blockIdx.z;
    const fp16* Bh = Bh_ + (size_t)z * zstride;
    OutT* C = (z == 0) ? C0 : ((z == 1) ? C1 : C2);
    const int mode = ACT ? z : 2;   // z0 silu, z1 sigmoid, z2 identity

    // prologue: fill stages 0,1
#pragma unroll
    for (int s = 0; s < NSTAGE - 1; s++) {
        uint32_t st = stage0 + s * STAGE_BYTES;
        load_tile(st,          Ah, m0, s * 64, tid);
        load_tile(st + 16384u, Bh, n0, s * 64, tid);
        asm volatile("cp.async.commit_group;" ::: "memory");
    }

    float acc[4][4][4];
#pragma unroll
    for (int a = 0; a < 4; a++)
#pragma unroll
        for (int b = 0; b < 4; b++)
#pragma unroll
            for (int c = 0; c < 4; c++) acc[a][b][c] = 0.f;

    const int aRow = lid & 15;
    const int aCg  = lid >> 4;
    const int bRow = (lid & 7) | ((lid & 16) >> 1);
    const int bCg  = (lid >> 3) & 1;
    const uint32_t aSwz = (uint32_t)(aRow & 7);
    const uint32_t bSwz = (uint32_t)(bRow & 7);
    uint32_t aOff[4], bOff[2];
#pragma unroll
    for (int mt = 0; mt < 4; mt++) aOff[mt] = (uint32_t)((wr * 64 + mt * 16 + aRow) * 128);
#pragma unroll
    for (int nt = 0; nt < 2; nt++) bOff[nt] = (uint32_t)((wc * 32 + nt * 16 + bRow) * 128);

    uint32_t ah[2][4][4], bhf[2][2][4];

#define LOAD_FRAGS(buf, sbase, ks_) do {                                        \
    uint32_t soA = (uint32_t)(((2 * (ks_) + aCg) ^ aSwz) << 4);                 \
    uint32_t soB = (uint32_t)(((2 * (ks_) + bCg) ^ bSwz) << 4);                 \
    _Pragma("unroll")                                                           \
    for (int mt = 0; mt < 4; mt++) {                                            \
        ldsm_x4(ah[buf][mt][0], ah[buf][mt][1], ah[buf][mt][2], ah[buf][mt][3], \
                (sbase) + aOff[mt] + soA);                                      \
    }                                                                           \
    _Pragma("unroll")                                                           \
    for (int nt = 0; nt < 2; nt++) {                                            \
        ldsm_x4(bhf[buf][nt][0], bhf[buf][nt][1], bhf[buf][nt][2],              \
                bhf[buf][nt][3], (sbase) + 16384u + bOff[nt] + soB);            \
    }                                                                           \
} while (0)

#define COMPUTE(buf) do {                                                       \
    _Pragma("unroll")                                                           \
    for (int mt = 0; mt < 4; mt++)                                              \
        _Pragma("unroll")                                                       \
        for (int nt = 0; nt < 4; nt++) {                                        \
            const uint32_t* bh2 = &bhf[buf][nt >> 1][(nt & 1) * 2];             \
            mma_fp16(acc[mt][nt], ah[buf][mt], bh2);                            \
        }                                                                       \
} while (0)

    for (int k = 0; k < 16; k++) {
        uint32_t sbase = stage0 + (uint32_t)(k % NSTAGE) * STAGE_BYTES;

        if (k <= 14) asm volatile("cp.async.wait_group 1;" ::: "memory");
        else         asm volatile("cp.async.wait_group 0;" ::: "memory");
        __syncthreads();   // all warps done with iter k-1 -> slot (k-1)%3 free

        int kn = k + 2;
        if (kn < 16) {
            uint32_t lbase = stage0 + (uint32_t)(kn % NSTAGE) * STAGE_BYTES;
            load_tile(lbase,          Ah, m0, kn * 64, tid);
            load_tile(lbase + 16384u, Bh, n0, kn * 64, tid);
            asm volatile("cp.async.commit_group;" ::: "memory");
        }

        LOAD_FRAGS(0, sbase, 0);
#pragma unroll
        for (int ks = 0; ks < 4; ks++) {
            int cur = ks & 1;
            if (ks < 3) LOAD_FRAGS((cur ^ 1), sbase, (ks + 1));
            COMPUTE(cur);
        }
    }

    // epilogue (optionally fused activation)
    const int g4 = lid >> 2;
    const int t4 = lid & 3;
#pragma unroll
    for (int mt = 0; mt < 4; mt++) {
        int row = m0 + wr * 64 + mt * 16 + g4;
#pragma unroll
        for (int nt = 0; nt < 4; nt++) {
            int col = n0 + wc * 32 + nt * 8 + t4 * 2;
            float v0 = ep_xform(acc[mt][nt][0], mode);
            float v1 = ep_xform(acc[mt][nt][1], mode);
            float v2 = ep_xform(acc[mt][nt][2], mode);
            float v3 = ep_xform(acc[mt][nt][3], mode);
            if constexpr (sizeof(OutT) == 2) {
                *(__half2*)((fp16*)C + (size_t)row * Hx + col)       = __floats2half2_rn(v0, v1);
                *(__half2*)((fp16*)C + (size_t)(row + 8) * Hx + col) = __floats2half2_rn(v2, v3);
            } else {
                *(float2*)((float*)C + (size_t)row * Hx + col)       = make_float2(v0, v1);
                *(float2*)((float*)C + (size_t)(row + 8) * Hx + col) = make_float2(v2, v3);
            }
        }
    }
}

// ---------------- fused fp32 -> fp16 conversions (x + all 4 weights) -------
#define NEc (Mx * Hx)
#define NWc (Hx * Hx)
__global__ void k_cvt_all(const float* __restrict__ x,  const float* __restrict__ Wi,
                          const float* __restrict__ Wf, const float* __restrict__ Wg,
                          const float* __restrict__ Wo) {
    int i = blockIdx.x * blockDim.x + threadIdx.x;
    if (i < NEc) {
        g_Xh[i] = __float2half_rn(x[i]);
    } else {
        int j = i - NEc;
        int y = j >> 20;                 // j / NWc
        int o = j & (NWc - 1);
        const float* s = (y == 0) ? Wi : (y == 1) ? Wf : (y == 2) ? Wg : Wo;
        fp16* d = (y < 3) ? (g_Wh + (size_t)y * NWc) : g_Woh;
        d[o] = __float2half_rn(s[o]);
    }
}

// pass 1: chunk-local scan over pre-activated f, silu_i.
// in_t = silu_i * (1 - f);  h = f*h + in;  p *= f.
__global__ void k_scan1() {
    int tid = blockIdx.x * blockDim.x + threadIdx.x;   // B*NCH*H = 262144
    int h  = tid & (Hx - 1);
    int bc = tid >> 10;          // b*NCH + c
    int b  = bc >> 6;
    int c  = bc & (NCH - 1);
    size_t base = ((size_t)(b * Sx + c * CH)) * Hx + h;
    float p = 1.f, hl = 0.f;
    for (int tb = 0; tb < CH; tb += 4) {
        float fr[4], ir[4];
#pragma unroll
        for (int j = 0; j < 4; j++) {
            size_t idx = base + (size_t)(tb + j) * Hx;
            fr[j] = __half2float(g_Yf[idx]);
            ir[j] = __half2float(g_Yi[idx]);
        }
#pragma unroll
        for (int j = 0; j < 4; j++) {
            float f  = fr[j];
            float in = ir[j] * (1.f - f);
            hl = f * hl + in;
            p  = p * f;
            fr[j] = p;
            ir[j] = hl;
        }
#pragma unroll
        for (int j = 0; j < 4; j++) {
            size_t idx = base + (size_t)(tb + j) * Hx;
            g_PH[idx] = __floats2half2_rn(fr[j], ir[j]);
        }
    }
    g_P[tid] = p;
    g_E[tid] = hl;
}

// pass 2: scan across chunks per channel (fp32)
__global__ void k_scan2() {
    int tid = blockIdx.x * blockDim.x + threadIdx.x;   // B*H = 4096
    int h = tid & (Hx - 1);
    int b = tid >> 10;
    float carry = 0.f;
#pragma unroll
    for (int c = 0; c < NCH; c++) {
        int idx = ((b * NCH + c) << 10) + h;
        g_Cr[idx] = carry;
        carry = g_P[idx] * carry + g_E[idx];
    }
}

// pass 3: h = h_local + cumprod(f)*carry; gh = g*h; fp16
__global__ void k_scan3(int n) {
    int i = blockIdx.x * blockDim.x + threadIdx.x;
    if (i < n) {
        int h = i & (Hx - 1);
        int s = (i >> 10) & (Sx - 1);
        int b = i >> 21;
        int c = s >> 5;                 // CH = 32
        float carry = g_Cr[((b * NCH + c) << 10) + h];
        __half2 ph = g_PH[i];
        float hv = __high2float(ph) + __low2float(ph) * carry;
        g_GH[i] = __float2half_rn(__half2float(g_Yg[i]) * hv);
    }
}

// ---------------- launch ----------------
extern "C" void kernel_launch(void* const* d_in, const int* in_sizes, int n_in,
                              void* d_out, int out_size) {
    const float* x  = (const float*)d_in[0];
    const float* Wi = (const float*)d_in[1];
    const float* Wf = (const float*)d_in[2];
    const float* Wg = (const float*)d_in[3];
    const float* Wo = (const float*)d_in[4];
    float* out = (float*)d_out;

    cudaFuncSetAttribute((const void*)k_gemm<fp16, true>,
                         cudaFuncAttributeMaxDynamicSharedMemorySize, GEMM_SMEM);
    cudaFuncSetAttribute((const void*)k_gemm<float, false>,
                         cudaFuncAttributeMaxDynamicSharedMemorySize, GEMM_SMEM);

    fp16 *Xh, *Wh, *Woh, *GH, *Yi, *Yf, *Yg;
    cudaGetSymbolAddress((void**)&Xh,  g_Xh);
    cudaGetSymbolAddress((void**)&Wh,  g_Wh);
    cudaGetSymbolAddress((void**)&Woh, g_Woh);
    cudaGetSymbolAddress((void**)&GH,  g_GH);
    cudaGetSymbolAddress((void**)&Yi,  g_Yi);
    cudaGetSymbolAddress((void**)&Yf,  g_Yf);
    cudaGetSymbolAddress((void**)&Yg,  g_Yg);

    const int NE = Mx * Hx;     // 8388608
    const int NW = Hx * Hx;     // 1048576

    // one conversion kernel for x + all weights
    k_cvt_all<<<(NE + 4 * NW) / 256, 256>>>(x, Wi, Wf, Wg, Wo);

    // GEMM1: Yi = silu(x@Wi^T), Yf = sigmoid(x@Wf^T), Yg = x@Wg^T
    dim3 g1(Hx / 128, Mx / 128, 3);
    k_gemm<fp16, true><<<g1, 256, GEMM_SMEM>>>(Xh, Wh, Yi, Yf, Yg, NW);

    // chunked linear recurrence
    k_scan1<<<(Bx * NCH * Hx) / 256, 256>>>();
    k_scan2<<<(Bx * Hx) / 256, 256>>>();
    k_scan3<<<NE / 256, 256>>>(NE);

    // GEMM2: out = (g*h) @ Wo^T (fp32 out)
    dim3 g2(Hx / 128, Mx / 128, 1);
    k_gemm<float, false><<<g2, 256, GEMM_SMEM>>>(GH, Woh, out, out, out, 0);
}

// round 8
// speedup vs baseline: 2.4632x; 1.0565x over previous
#include <cuda_runtime.h>
#include <cuda_fp16.h>
#include <cstdint>

typedef __half fp16;

#define Bx 4
#define Sx 2048
#define Hx 1024
#define Mx 8192            // B*S
#define CH 32              // scan chunk length
#define NCH 64             // S / CH

// ---------------- device scratch ----------------
__device__ __align__(256) fp16  g_Xh[Mx * Hx];
__device__ __align__(256) fp16  g_Wh[3 * Hx * Hx];    // [Wi, Wf, Wg] fp16
__device__ __align__(256) fp16  g_Woh[Hx * Hx];
__device__ __align__(256) fp16  g_Yi[Mx * Hx];        // silu(i_raw)   (fp16)
__device__ __align__(256) fp16  g_Yf[Mx * Hx];        // sigmoid(f_raw)(fp16)
__device__ __align__(256) fp16  g_Yg[Mx * Hx];        // g raw (fp16)
__device__ __align__(256) __half2 g_PH[Mx * Hx];      // {cumprod(f), h_local}
__device__ __align__(256) fp16  g_GH[Mx * Hx];
__device__ float g_P[Bx * NCH * Hx];
__device__ float g_E[Bx * NCH * Hx];
__device__ float g_Cr[Bx * NCH * Hx];

// ---------------- PTX helpers ----------------
__device__ __forceinline__ uint32_t smem_u32(const void* p) {
    uint32_t a;
    asm("{ .reg .u64 t; cvta.to.shared.u64 t, %1; cvt.u32.u64 %0, t; }" : "=r"(a) : "l"(p));
    return a;
}

__device__ __forceinline__ void ldsm_x4(uint32_t& r0, uint32_t& r1, uint32_t& r2,
                                        uint32_t& r3, uint32_t addr) {
    asm volatile("ldmatrix.sync.aligned.m8n8.x4.shared.b16 {%0,%1,%2,%3}, [%4];"
                 : "=r"(r0), "=r"(r1), "=r"(r2), "=r"(r3) : "r"(addr));
}

__device__ __forceinline__ void mma_fp16(float* c, const uint32_t* a, const uint32_t* b) {
    asm volatile(
        "mma.sync.aligned.m16n8k16.row.col.f32.f16.f16.f32 "
        "{%0,%1,%2,%3}, {%4,%5,%6,%7}, {%8,%9}, {%0,%1,%2,%3};"
        : "+f"(c[0]), "+f"(c[1]), "+f"(c[2]), "+f"(c[3])
        : "r"(a[0]), "r"(a[1]), "r"(a[2]), "r"(a[3]), "r"(b[0]), "r"(b[1]));
}

// epilogue transforms: mode 0 = silu, 1 = sigmoid, 2 = identity
__device__ __forceinline__ float ep_xform(float v, int mode) {
    if (mode == 0) return v / (1.f + __expf(-v));          // silu
    if (mode == 1) return 1.f / (1.f + __expf(-v));        // sigmoid
    return v;
}

// ---------------- GEMM: C[M,N] = A[M,K] @ W[N,K]^T, fp16, fp32 accum -------
// CTA tile 128x128, K-chunk 64, 3-stage cp.async pipeline (loads 2 ahead),
// 8 warps (2x4), warp tile 64x32, frag double-buffer, 2 CTAs/SM.
#define STAGE_BYTES 32768u          // 2 tiles x (128 x 64 fp16)
#define NSTAGE 3
#define GEMM_SMEM   (1024 + NSTAGE * 32768)

__device__ __forceinline__ void load_tile(uint32_t tb, const fp16* __restrict__ src,
                                          int row0, int k0, int tid) {
    const char* gbase = (const char*)(src + (size_t)row0 * Hx + k0);
#pragma unroll
    for (int i = 0; i < 4; i++) {
        int gid = tid + i * 256;        // 1024 granules of 16B
        int row = gid >> 3;
        int g   = gid & 7;
        const char* gp = gbase + (size_t)row * (Hx * 2) + g * 16;
        uint32_t sp = tb + (uint32_t)(row * 128) + (uint32_t)((g ^ (row & 7)) << 4);
        asm volatile("cp.async.cg.shared.global [%0], [%1], 16;"
                     :: "r"(sp), "l"(gp) : "memory");
    }
}

template <typename OutT, bool ACT>
__global__ void __launch_bounds__(256, 2) k_gemm(
    const fp16* __restrict__ Ah,
    const fp16* __restrict__ Bh_,
    OutT* __restrict__ C0, OutT* __restrict__ C1, OutT* __restrict__ C2,
    int zstride)
{
    extern __shared__ char smem_raw[];
    uint32_t sb     = smem_u32(smem_raw);
    uint32_t stage0 = (sb + 1023u) & ~1023u;

    const int tid = threadIdx.x;
    const int wid = tid >> 5;
    const int lid = tid & 31;
    const int wr  = wid >> 2;       // 0-1  -> m offset wr*64
    const int wc  = wid & 3;        // 0-3  -> n offset wc*32
    const int n0  = blockIdx.x * 128;
    const int m0  = blockIdx.y * 128;
    const int z   = blockIdx.z;
    const fp16* Bh = Bh_ + (size_t)z * zstride;
    OutT* C = (z == 0) ? C0 : ((z == 1) ? C1 : C2);
    const int mode = ACT ? z : 2;   // z0 silu, z1 sigmoid, z2 identity

    // prologue: fill stages 0,1
#pragma unroll
    for (int s = 0; s < NSTAGE - 1; s++) {
        uint32_t st = stage0 + s * STAGE_BYTES;
        load_tile(st,          Ah, m0, s * 64, tid);
        load_tile(st + 16384u, Bh, n0, s * 64, tid);
        asm volatile("cp.async.commit_group;" ::: "memory");
    }

    float acc[4][4][4];
#pragma unroll
    for (int a = 0; a < 4; a++)
#pragma unroll
        for (int b = 0; b < 4; b++)
#pragma unroll
            for (int c = 0; c < 4; c++) acc[a][b][c] = 0.f;

    const int aRow = lid & 15;
    const int aCg  = lid >> 4;
    const int bRow = (lid & 7) | ((lid & 16) >> 1);
    const int bCg  = (lid >> 3) & 1;
    const uint32_t aSwz = (uint32_t)(aRow & 7);
    const uint32_t bSwz = (uint32_t)(bRow & 7);
    uint32_t aOff[4], bOff[2];
#pragma unroll
    for (int mt = 0; mt < 4; mt++) aOff[mt] = (uint32_t)((wr * 64 + mt * 16 + aRow) * 128);
#pragma unroll
    for (int nt = 0; nt < 2; nt++) bOff[nt] = (uint32_t)((wc * 32 + nt * 16 + bRow) * 128);

    uint32_t ah[2][4][4], bhf[2][2][4];

#define LOAD_FRAGS(buf, sbase, ks_) do {                                        \
    uint32_t soA = (uint32_t)(((2 * (ks_) + aCg) ^ aSwz) << 4);                 \
    uint32_t soB = (uint32_t)(((2 * (ks_) + bCg) ^ bSwz) << 4);                 \
    _Pragma("unroll")                                                           \
    for (int mt = 0; mt < 4; mt++) {                                            \
        ldsm_x4(ah[buf][mt][0], ah[buf][mt][1], ah[buf][mt][2], ah[buf][mt][3], \
                (sbase) + aOff[mt] + soA);                                      \
    }                                                                           \
    _Pragma("unroll")                                                           \
    for (int nt = 0; nt < 2; nt++) {                                            \
        ldsm_x4(bhf[buf][nt][0], bhf[buf][nt][1], bhf[buf][nt][2],              \
                bhf[buf][nt][3], (sbase) + 16384u + bOff[nt] + soB);            \
    }                                                                           \
} while (0)

#define COMPUTE(buf) do {                                                       \
    _Pragma("unroll")                                                           \
    for (int mt = 0; mt < 4; mt++)                                              \
        _Pragma("unroll")                                                       \
        for (int nt = 0; nt < 4; nt++) {                                        \
            const uint32_t* bh2 = &bhf[buf][nt >> 1][(nt & 1) * 2];             \
            mma_fp16(acc[mt][nt], ah[buf][mt], bh2);                            \
        }                                                                       \
} while (0)

    for (int k = 0; k < 16; k++) {
        uint32_t sbase = stage0 + (uint32_t)(k % NSTAGE) * STAGE_BYTES;

        if (k <= 14) asm volatile("cp.async.wait_group 1;" ::: "memory");
        else         asm volatile("cp.async.wait_group 0;" ::: "memory");
        __syncthreads();   // all warps done with iter k-1 -> slot (k-1)%3 free

        int kn = k + 2;
        if (kn < 16) {
            uint32_t lbase = stage0 + (uint32_t)(kn % NSTAGE) * STAGE_BYTES;
            load_tile(lbase,          Ah, m0, kn * 64, tid);
            load_tile(lbase + 16384u, Bh, n0, kn * 64, tid);
            asm volatile("cp.async.commit_group;" ::: "memory");
        }

        LOAD_FRAGS(0, sbase, 0);
#pragma unroll
        for (int ks = 0; ks < 4; ks++) {
            int cur = ks & 1;
            if (ks < 3) LOAD_FRAGS((cur ^ 1), sbase, (ks + 1));
            COMPUTE(cur);
        }
    }

    // epilogue (optionally fused activation)
    const int g4 = lid >> 2;
    const int t4 = lid & 3;
#pragma unroll
    for (int mt = 0; mt < 4; mt++) {
        int row = m0 + wr * 64 + mt * 16 + g4;
#pragma unroll
        for (int nt = 0; nt < 4; nt++) {
            int col = n0 + wc * 32 + nt * 8 + t4 * 2;
            float v0 = ep_xform(acc[mt][nt][0], mode);
            float v1 = ep_xform(acc[mt][nt][1], mode);
            float v2 = ep_xform(acc[mt][nt][2], mode);
            float v3 = ep_xform(acc[mt][nt][3], mode);
            if constexpr (sizeof(OutT) == 2) {
                *(__half2*)((fp16*)C + (size_t)row * Hx + col)       = __floats2half2_rn(v0, v1);
                *(__half2*)((fp16*)C + (size_t)(row + 8) * Hx + col) = __floats2half2_rn(v2, v3);
            } else {
                *(float2*)((float*)C + (size_t)row * Hx + col)       = make_float2(v0, v1);
                *(float2*)((float*)C + (size_t)(row + 8) * Hx + col) = make_float2(v2, v3);
            }
        }
    }
}

// ---------------- fused fp32 -> fp16 conversions (x + all 4 weights) -------
#define NEc (Mx * Hx)
#define NWc (Hx * Hx)
__global__ void k_cvt_all(const float* __restrict__ x,  const float* __restrict__ Wi,
                          const float* __restrict__ Wf, const float* __restrict__ Wg,
                          const float* __restrict__ Wo) {
    int i = blockIdx.x * blockDim.x + threadIdx.x;
    if (i < NEc) {
        g_Xh[i] = __float2half_rn(x[i]);
    } else {
        int j = i - NEc;
        int y = j >> 20;                 // j / NWc
        int o = j & (NWc - 1);
        const float* s = (y == 0) ? Wi : (y == 1) ? Wf : (y == 2) ? Wg : Wo;
        fp16* d = (y < 3) ? (g_Wh + (size_t)y * NWc) : g_Woh;
        d[o] = __float2half_rn(s[o]);
    }
}

// pass 1: chunk-local scan over pre-activated f, silu_i.
__global__ void k_scan1() {
    int tid = blockIdx.x * blockDim.x + threadIdx.x;   // B*NCH*H = 262144
    int h  = tid & (Hx - 1);
    int bc = tid >> 10;          // b*NCH + c
    int b  = bc >> 6;
    int c  = bc & (NCH - 1);
    size_t base = ((size_t)(b * Sx + c * CH)) * Hx + h;
    float p = 1.f, hl = 0.f;
    for (int tb = 0; tb < CH; tb += 4) {
        float fr[4], ir[4];
#pragma unroll
        for (int j = 0; j < 4; j++) {
            size_t idx = base + (size_t)(tb + j) * Hx;
            fr[j] = __half2float(g_Yf[idx]);
            ir[j] = __half2float(g_Yi[idx]);
        }
#pragma unroll
        for (int j = 0; j < 4; j++) {
            float f  = fr[j];
            float in = ir[j] * (1.f - f);
            hl = f * hl + in;
            p  = p * f;
            fr[j] = p;
            ir[j] = hl;
        }
#pragma unroll
        for (int j = 0; j < 4; j++) {
            size_t idx = base + (size_t)(tb + j) * Hx;
            g_PH[idx] = __floats2half2_rn(fr[j], ir[j]);
        }
    }
    g_P[tid] = p;
    g_E[tid] = hl;
}

// pass 2: warp-parallel exclusive scan of affine maps (p,e) across the 64
// chunks of each channel. One warp per (b,h) channel; 2 chunks per lane.
// Composition (apply A then B): (pA,eA)∘(pB,eB) = (pA·pB, pB·eA + eB).
__global__ void k_scan2() {
    int gt   = blockIdx.x * blockDim.x + threadIdx.x;
    int gw   = gt >> 5;                  // warp id = channel id, 0..4095
    int lane = gt & 31;
    int b = gw >> 10;
    int h = gw & (Hx - 1);
    int c0   = 2 * lane;
    int idx0 = ((b * NCH + c0) << 10) + h;
    int idx1 = idx0 + (1 << 10);

    float p0 = g_P[idx0], e0 = g_E[idx0];
    float p1 = g_P[idx1], e1 = g_E[idx1];

    // compose this lane's two chunks
    float pp = p0 * p1;
    float ee = p1 * e0 + e1;

    // inclusive warp scan (earlier lanes compose first)
#pragma unroll
    for (int d = 1; d < 32; d <<= 1) {
        float pprev = __shfl_up_sync(0xffffffffu, pp, d);
        float eprev = __shfl_up_sync(0xffffffffu, ee, d);
        if (lane >= d) {
            ee = pp * eprev + ee;       // uses pre-update pp
            pp = pprev * pp;
        }
    }
    // exclusive prefix for this lane
    float ex = __shfl_up_sync(0xffffffffu, ee, 1);
    if (lane == 0) ex = 0.f;

    // carry into chunk c0 (h starts at 0 => carry = E-part of prefix)
    float carry0 = ex;
    float carry1 = p0 * carry0 + e0;
    g_Cr[idx0] = carry0;
    g_Cr[idx1] = carry1;
}

// pass 3: h = h_local + cumprod(f)*carry; gh = g*h; fp16
__global__ void k_scan3(int n) {
    int i = blockIdx.x * blockDim.x + threadIdx.x;
    if (i < n) {
        int h = i & (Hx - 1);
        int s = (i >> 10) & (Sx - 1);
        int b = i >> 21;
        int c = s >> 5;                 // CH = 32
        float carry = g_Cr[((b * NCH + c) << 10) + h];
        __half2 ph = g_PH[i];
        float hv = __high2float(ph) + __low2float(ph) * carry;
        g_GH[i] = __float2half_rn(__half2float(g_Yg[i]) * hv);
    }
}

// ---------------- launch ----------------
extern "C" void kernel_launch(void* const* d_in, const int* in_sizes, int n_in,
                              void* d_out, int out_size) {
    const float* x  = (const float*)d_in[0];
    const float* Wi = (const float*)d_in[1];
    const float* Wf = (const float*)d_in[2];
    const float* Wg = (const float*)d_in[3];
    const float* Wo = (const float*)d_in[4];
    float* out = (float*)d_out;

    cudaFuncSetAttribute((const void*)k_gemm<fp16, true>,
                         cudaFuncAttributeMaxDynamicSharedMemorySize, GEMM_SMEM);
    cudaFuncSetAttribute((const void*)k_gemm<float, false>,
                         cudaFuncAttributeMaxDynamicSharedMemorySize, GEMM_SMEM);

    fp16 *Xh, *Wh, *Woh, *GH, *Yi, *Yf, *Yg;
    cudaGetSymbolAddress((void**)&Xh,  g_Xh);
    cudaGetSymbolAddress((void**)&Wh,  g_Wh);
    cudaGetSymbolAddress((void**)&Woh, g_Woh);
    cudaGetSymbolAddress((void**)&GH,  g_GH);
    cudaGetSymbolAddress((void**)&Yi,  g_Yi);
    cudaGetSymbolAddress((void**)&Yf,  g_Yf);
    cudaGetSymbolAddress((void**)&Yg,  g_Yg);

    const int NE = Mx * Hx;     // 8388608
    const int NW = Hx * Hx;     // 1048576

    // one conversion kernel for x + all weights
    k_cvt_all<<<(NE + 4 * NW) / 256, 256>>>(x, Wi, Wf, Wg, Wo);

    // GEMM1: Yi = silu(x@Wi^T), Yf = sigmoid(x@Wf^T), Yg = x@Wg^T
    dim3 g1(Hx / 128, Mx / 128, 3);
    k_gemm<fp16, true><<<g1, 256, GEMM_SMEM>>>(Xh, Wh, Yi, Yf, Yg, NW);

    // chunked linear recurrence
    k_scan1<<<(Bx * NCH * Hx) / 256, 256>>>();
    k_scan2<<<(Bx * Hx * 32) / 256, 256>>>();   // one warp per channel
    k_scan3<<<NE / 256, 256>>>(NE);

    // GEMM2: out = (g*h) @ Wo^T (fp32 out)
    dim3 g2(Hx / 128, Mx / 128, 1);
    k_gemm<float, false><<<g2, 256, GEMM_SMEM>>>(GH, Woh, out, out, out, 0);
}

// round 10
// speedup vs baseline: 2.6732x; 1.0853x over previous
#include <cuda_runtime.h>
#include <cuda_fp16.h>
#include <cstdint>

typedef __half fp16;

#define Bx 4
#define Sx 2048
#define Hx 1024
#define Mx 8192            // B*S
#define CH 32              // scan chunk length
#define NCH 64             // S / CH
#define NPERS 304          // persistent grid: 2 CTAs/SM x 152 SMs

// ---------------- device scratch ----------------
__device__ __align__(256) fp16  g_Xh[Mx * Hx];
__device__ __align__(256) fp16  g_Wh[3 * Hx * Hx];    // [Wi, Wf, Wg] fp16
__device__ __align__(256) fp16  g_Woh[Hx * Hx];
__device__ __align__(256) fp16  g_Yi[Mx * Hx];        // silu(i_raw)   (fp16)
__device__ __align__(256) fp16  g_Yf[Mx * Hx];        // sigmoid(f_raw)(fp16)
__device__ __align__(256) fp16  g_Yg[Mx * Hx];        // g raw (fp16)
__device__ __align__(256) __half2 g_PH[Mx * Hx];      // {cumprod(f), h_local}
__device__ __align__(256) fp16  g_GH[Mx * Hx];
__device__ float g_P[Bx * NCH * Hx];
__device__ float g_E[Bx * NCH * Hx];
__device__ float g_Cr[Bx * NCH * Hx];

// ---------------- PTX helpers ----------------
__device__ __forceinline__ uint32_t smem_u32(const void* p) {
    uint32_t a;
    asm("{ .reg .u64 t; cvta.to.shared.u64 t, %1; cvt.u32.u64 %0, t; }" : "=r"(a) : "l"(p));
    return a;
}

__device__ __forceinline__ uint32_t h2_bits(__half2 h) {
    uint32_t u;
    *(__half2*)&u = h;
    return u;
}

__device__ __forceinline__ void ldsm_x4(uint32_t& r0, uint32_t& r1, uint32_t& r2,
                                        uint32_t& r3, uint32_t addr) {
    asm volatile("ldmatrix.sync.aligned.m8n8.x4.shared.b16 {%0,%1,%2,%3}, [%4];"
                 : "=r"(r0), "=r"(r1), "=r"(r2), "=r"(r3) : "r"(addr));
}

__device__ __forceinline__ void mma_fp16(float* c, const uint32_t* a, const uint32_t* b) {
    asm volatile(
        "mma.sync.aligned.m16n8k16.row.col.f32.f16.f16.f32 "
        "{%0,%1,%2,%3}, {%4,%5,%6,%7}, {%8,%9}, {%0,%1,%2,%3};"
        : "+f"(c[0]), "+f"(c[1]), "+f"(c[2]), "+f"(c[3])
        : "r"(a[0]), "r"(a[1]), "r"(a[2]), "r"(a[3]), "r"(b[0]), "r"(b[1]));
}

// epilogue transforms: mode 0 = silu, 1 = sigmoid, 2 = identity
__device__ __forceinline__ float ep_xform(float v, int mode) {
    if (mode == 0) return v / (1.f + __expf(-v));          // silu
    if (mode == 1) return 1.f / (1.f + __expf(-v));        // sigmoid
    return v;
}

// ---------------- persistent GEMM: C[M,N] = A[M,K] @ W[N,K]^T ---------------
// CTA tile 128x128, K-chunk 64, 3-slot cp.async pipeline with a CONTINUOUS
// global iteration counter across tiles (no drain at tile boundaries).
// 8 warps (2x4), warp tile 64x32, frag double-buffer, 2 CTAs/SM.
#define STAGE_BYTES 32768u          // 2 tiles x (128 x 64 fp16)
#define GEMM_SMEM   (1024 + 3 * 32768)

__device__ __forceinline__ void load_tile(uint32_t tb, const fp16* __restrict__ src,
                                          int row0, int k0, int tid) {
    const char* gbase = (const char*)(src + (size_t)row0 * Hx + k0);
#pragma unroll
    for (int i = 0; i < 4; i++) {
        int gid = tid + i * 256;        // 1024 granules of 16B
        int row = gid >> 3;
        int g   = gid & 7;
        const char* gp = gbase + (size_t)row * (Hx * 2) + g * 16;
        uint32_t sp = tb + (uint32_t)(row * 128) + (uint32_t)((g ^ (row & 7)) << 4);
        asm volatile("cp.async.cg.shared.global [%0], [%1], 16;"
                     :: "r"(sp), "l"(gp) : "memory");
    }
}

// tile index -> coords: z = t/512, m0 = ((t%512)/8)*128, n0 = (t%8)*128
struct TileC { int m0, n0, z; };
__device__ __forceinline__ TileC tile_coords(int t) {
    TileC c;
    c.z  = t >> 9;
    int r = t & 511;
    c.m0 = (r >> 3) << 7;
    c.n0 = (r & 7) << 7;
    return c;
}

template <typename OutT, bool ACT>
__global__ void __launch_bounds__(256, 2) k_gemm_p(
    const fp16* __restrict__ Ah,
    const fp16* __restrict__ Bh_,
    OutT* __restrict__ C0, OutT* __restrict__ C1, OutT* __restrict__ C2,
    int zstride, int ntiles)
{
    extern __shared__ char smem_raw[];
    uint32_t sb     = smem_u32(smem_raw);
    uint32_t stage0 = (sb + 1023u) & ~1023u;

    const int tid = threadIdx.x;
    const int wid = tid >> 5;
    const int lid = tid & 31;
    const int wr  = wid >> 2;       // 0-1  -> m offset wr*64
    const int wc  = wid & 3;        // 0-3  -> n offset wc*32
    const int bid = blockIdx.x;
    if (bid >= ntiles) return;
    const int T = (ntiles - 1 - bid) / NPERS + 1;   // my tile count

    const int aRow = lid & 15;
    const int aCg  = lid >> 4;
    const int bRow = (lid & 7) | ((lid & 16) >> 1);
    const int bCg  = (lid >> 3) & 1;
    const uint32_t aSwz = (uint32_t)(aRow & 7);
    const uint32_t bSwz = (uint32_t)(bRow & 7);
    uint32_t aOff[4], bOff[2];
#pragma unroll
    for (int mt = 0; mt < 4; mt++) aOff[mt] = (uint32_t)((wr * 64 + mt * 16 + aRow) * 128);
#pragma unroll
    for (int nt = 0; nt < 2; nt++) bOff[nt] = (uint32_t)((wc * 32 + nt * 16 + bRow) * 128);

    uint32_t ah[2][4][4], bhf[2][2][4];

#define LOAD_FRAGS(buf, sbase, ks_) do {                                        \
    uint32_t soA = (uint32_t)(((2 * (ks_) + aCg) ^ aSwz) << 4);                 \
    uint32_t soB = (uint32_t)(((2 * (ks_) + bCg) ^ bSwz) << 4);                 \
    _Pragma("unroll")                                                           \
    for (int mt = 0; mt < 4; mt++) {                                            \
        ldsm_x4(ah[buf][mt][0], ah[buf][mt][1], ah[buf][mt][2], ah[buf][mt][3], \
                (sbase) + aOff[mt] + soA);                                      \
    }                                                                           \
    _Pragma("unroll")                                                           \
    for (int nt = 0; nt < 2; nt++) {                                            \
        ldsm_x4(bhf[buf][nt][0], bhf[buf][nt][1], bhf[buf][nt][2],              \
                bhf[buf][nt][3], (sbase) + 16384u + bOff[nt] + soB);            \
    }                                                                           \
} while (0)

#define COMPUTE(buf) do {                                                       \
    _Pragma("unroll")                                                           \
    for (int mt = 0; mt < 4; mt++)                                              \
        _Pragma("unroll")                                                       \
        for (int nt = 0; nt < 4; nt++) {                                        \
            const uint32_t* bh2 = &bhf[buf][nt >> 1][(nt & 1) * 2];             \
            mma_fp16(acc[mt][nt], ah[buf][mt], bh2);                            \
        }                                                                       \
} while (0)

    // prologue: global iters 0,1 = tile0 k=0,1
    TileC cur = tile_coords(bid);
    const fp16* curB = Bh_ + (size_t)cur.z * zstride;
#pragma unroll
    for (int s = 0; s < 2; s++) {
        uint32_t st = stage0 + s * STAGE_BYTES;
        load_tile(st,          Ah,   cur.m0, s * 64, tid);
        load_tile(st + 16384u, curB, cur.n0, s * 64, tid);
        asm volatile("cp.async.commit_group;" ::: "memory");
    }

    int it = 0;                              // continuous global iteration
    for (int j = 0; j < T; j++) {
        TileC nxt;
        const fp16* nxtB = nullptr;
        bool have_nxt = (j + 1 < T);
        if (have_nxt) {
            nxt  = tile_coords(bid + (j + 1) * NPERS);
            nxtB = Bh_ + (size_t)nxt.z * zstride;
        }

        float acc[4][4][4];
#pragma unroll
        for (int a = 0; a < 4; a++)
#pragma unroll
            for (int b = 0; b < 4; b++)
#pragma unroll
                for (int c = 0; c < 4; c++) acc[a][b][c] = 0.f;

        for (int k = 0; k < 16; k++, it++) {
            uint32_t sbase = stage0 + (uint32_t)(it % 3) * STAGE_BYTES;

            if (j == T - 1 && k == 15)
                asm volatile("cp.async.wait_group 0;" ::: "memory");
            else
                asm volatile("cp.async.wait_group 1;" ::: "memory");
            __syncthreads();   // all warps done with iter it-1 -> slot (it-1)%3 free

            // issue loads for global iter it+2 into slot (it+2)%3
            uint32_t lbase = stage0 + (uint32_t)((it + 2) % 3) * STAGE_BYTES;
            if (k < 14) {
                load_tile(lbase,          Ah,   cur.m0, (k + 2) * 64, tid);
                load_tile(lbase + 16384u, curB, cur.n0, (k + 2) * 64, tid);
                asm volatile("cp.async.commit_group;" ::: "memory");
            } else if (have_nxt) {
                load_tile(lbase,          Ah,   nxt.m0, (k - 14) * 64, tid);
                load_tile(lbase + 16384u, nxtB, nxt.n0, (k - 14) * 64, tid);
                asm volatile("cp.async.commit_group;" ::: "memory");
            }

            LOAD_FRAGS(0, sbase, 0);
#pragma unroll
            for (int ks = 0; ks < 4; ks++) {
                int cb = ks & 1;
                if (ks < 3) LOAD_FRAGS((cb ^ 1), sbase, (ks + 1));
                COMPUTE(cb);
            }
        }

        // epilogue (registers -> gmem only; overlaps in-flight cp.async)
        OutT* C = (cur.z == 0) ? C0 : ((cur.z == 1) ? C1 : C2);
        const int mode = ACT ? cur.z : 2;
        const int g4 = lid >> 2;
        const int t4 = lid & 3;
#pragma unroll
        for (int mt = 0; mt < 4; mt++) {
            int row = cur.m0 + wr * 64 + mt * 16 + g4;
#pragma unroll
            for (int nt = 0; nt < 4; nt++) {
                int col = cur.n0 + wc * 32 + nt * 8 + t4 * 2;
                float v0 = ep_xform(acc[mt][nt][0], mode);
                float v1 = ep_xform(acc[mt][nt][1], mode);
                float v2 = ep_xform(acc[mt][nt][2], mode);
                float v3 = ep_xform(acc[mt][nt][3], mode);
                if constexpr (sizeof(OutT) == 2) {
                    *(__half2*)((fp16*)C + (size_t)row * Hx + col)       = __floats2half2_rn(v0, v1);
                    *(__half2*)((fp16*)C + (size_t)(row + 8) * Hx + col) = __floats2half2_rn(v2, v3);
                } else {
                    *(float2*)((float*)C + (size_t)row * Hx + col)       = make_float2(v0, v1);
                    *(float2*)((float*)C + (size_t)(row + 8) * Hx + col) = make_float2(v2, v3);
                }
            }
        }

        cur = nxt;
        curB = nxtB;
    }
}

// ---------------- fused fp32 -> fp16 conversions, x4 vectorized ------------
#define NEc (Mx * Hx)
#define NWc (Hx * Hx)
__global__ void k_cvt_all(const float* __restrict__ x,  const float* __restrict__ Wi,
                          const float* __restrict__ Wf, const float* __restrict__ Wg,
                          const float* __restrict__ Wo) {
    int i = blockIdx.x * blockDim.x + threadIdx.x;      // over (NE + 4NW)/4
    const float* s;
    fp16* d;
    int o;
    if (i < NEc / 4) {
        s = x; d = g_Xh; o = i;
    } else {
        int j = i - NEc / 4;
        int y = j >> 18;                 // j / (NWc/4)
        o = j & (NWc / 4 - 1);
        s = (y == 0) ? Wi : (y == 1) ? Wf : (y == 2) ? Wg : Wo;
        d = (y < 3) ? (g_Wh + (size_t)y * NWc) : g_Woh;
    }
    float4 v = ((const float4*)s)[o];
    __half2 h0 = __floats2half2_rn(v.x, v.y);
    __half2 h1 = __floats2half2_rn(v.z, v.w);
    ((uint2*)d)[o] = make_uint2(h2_bits(h0), h2_bits(h1));
}

// pass 1: chunk-local scan, 2 h-channels per thread (half2 path)
__global__ void k_scan1() {
    int tid = blockIdx.x * blockDim.x + threadIdx.x;   // B*NCH*H/2 = 131072
    int h2 = tid & 511;          // h-pair
    int bc = tid >> 9;           // b*NCH + c
    size_t base2 = ((size_t)((bc >> 6) * Sx + (bc & (NCH - 1)) * CH)) * (Hx / 2) + h2;
    const __half2* Yf2 = (const __half2*)g_Yf;
    const __half2* Yi2 = (const __half2*)g_Yi;
    float p0 = 1.f, hl0 = 0.f, p1 = 1.f, hl1 = 0.f;
#pragma unroll 4
    for (int t = 0; t < CH; t++) {
        size_t idx = base2 + (size_t)t * (Hx / 2);
        float2 f2 = __half22float2(Yf2[idx]);
        float2 i2 = __half22float2(Yi2[idx]);
        hl0 = f2.x * hl0 + i2.x * (1.f - f2.x);
        p0  = p0 * f2.x;
        hl1 = f2.y * hl1 + i2.y * (1.f - f2.y);
        p1  = p1 * f2.y;
        __half2 ph0 = __floats2half2_rn(p0, hl0);
        __half2 ph1 = __floats2half2_rn(p1, hl1);
        ((uint2*)g_PH)[idx] = make_uint2(h2_bits(ph0), h2_bits(ph1));
    }
    int sidx = (bc << 10) + 2 * h2;
    *(float2*)(g_P + sidx) = make_float2(p0, p1);
    *(float2*)(g_E + sidx) = make_float2(hl0, hl1);
}

// pass 2: warp-parallel scan of affine maps across 64 chunks per channel
__global__ void k_scan2() {
    int gt   = blockIdx.x * blockDim.x + threadIdx.x;
    int gw   = gt >> 5;                  // channel id, 0..4095
    int lane = gt & 31;
    int b = gw >> 10;
    int h = gw & (Hx - 1);
    int c0   = 2 * lane;
    int idx0 = ((b * NCH + c0) << 10) + h;
    int idx1 = idx0 + (1 << 10);

    float p0 = g_P[idx0], e0 = g_E[idx0];
    float p1 = g_P[idx1], e1 = g_E[idx1];
    float pp = p0 * p1;
    float ee = p1 * e0 + e1;

#pragma unroll
    for (int d = 1; d < 32; d <<= 1) {
        float pprev = __shfl_up_sync(0xffffffffu, pp, d);
        float eprev = __shfl_up_sync(0xffffffffu, ee, d);
        if (lane >= d) {
            ee = pp * eprev + ee;
            pp = pprev * pp;
        }
    }
    float ex = __shfl_up_sync(0xffffffffu, ee, 1);
    if (lane == 0) ex = 0.f;

    float carry0 = ex;
    float carry1 = p0 * carry0 + e0;
    g_Cr[idx0] = carry0;
    g_Cr[idx1] = carry1;
}

// pass 3: h = h_local + cumprod*carry; gh = g*h; 2 channels per thread
__global__ void k_scan3() {
    int i = blockIdx.x * blockDim.x + threadIdx.x;     // NE/2
    int h2 = i & 511;
    int s = (i >> 9) & (Sx - 1);
    int b = i >> 20;
    int c = s >> 5;                 // CH = 32
    float2 carry = *(float2*)(g_Cr + ((b * NCH + c) << 10) + 2 * h2);
    uint2 phu = ((const uint2*)g_PH)[i];
    __half2 ph0 = *(__half2*)&phu.x;
    __half2 ph1 = *(__half2*)&phu.y;
    float hv0 = __high2float(ph0) + __low2float(ph0) * carry.x;
    float hv1 = __high2float(ph1) + __low2float(ph1) * carry.y;
    float2 g2 = __half22float2(((const __half2*)g_Yg)[i]);
    ((__half2*)g_GH)[i] = __floats2half2_rn(g2.x * hv0, g2.y * hv1);
}

// ---------------- launch ----------------
extern "C" void kernel_launch(void* const* d_in, const int* in_sizes, int n_in,
                              void* d_out, int out_size) {
    const float* x  = (const float*)d_in[0];
    const float* Wi = (const float*)d_in[1];
    const float* Wf = (const float*)d_in[2];
    const float* Wg = (const float*)d_in[3];
    const float* Wo = (const float*)d_in[4];
    float* out = (float*)d_out;

    cudaFuncSetAttribute((const void*)k_gemm_p<fp16, true>,
                         cudaFuncAttributeMaxDynamicSharedMemorySize, GEMM_SMEM);
    cudaFuncSetAttribute((const void*)k_gemm_p<float, false>,
                         cudaFuncAttributeMaxDynamicSharedMemorySize, GEMM_SMEM);

    fp16 *Xh, *Wh, *Woh, *GH, *Yi, *Yf, *Yg;
    cudaGetSymbolAddress((void**)&Xh,  g_Xh);
    cudaGetSymbolAddress((void**)&Wh,  g_Wh);
    cudaGetSymbolAddress((void**)&Woh, g_Woh);
    cudaGetSymbolAddress((void**)&GH,  g_GH);
    cudaGetSymbolAddress((void**)&Yi,  g_Yi);
    cudaGetSymbolAddress((void**)&Yf,  g_Yf);
    cudaGetSymbolAddress((void**)&Yg,  g_Yg);

    const int NE = Mx * Hx;     // 8388608
    const int NW = Hx * Hx;     // 1048576

    // conversions (x4 vectorized)
    k_cvt_all<<<(NE / 4 + NW) / 256, 256>>>(x, Wi, Wf, Wg, Wo);

    // GEMM1 (persistent): Yi = silu(x@Wi^T), Yf = sigmoid(x@Wf^T), Yg = x@Wg^T
    k_gemm_p<fp16, true><<<NPERS, 256, GEMM_SMEM>>>(Xh, Wh, Yi, Yf, Yg, NW, 1536);

    // chunked linear recurrence
    k_scan1<<<(Bx * NCH * Hx / 2) / 256, 256>>>();
    k_scan2<<<(Bx * Hx * 32) / 256, 256>>>();
    k_scan3<<<(NE / 2) / 256, 256>>>();

    // GEMM2 (persistent): out = (g*h) @ Wo^T
    k_gemm_p<float, false><<<NPERS, 256, GEMM_SMEM>>>(GH, Woh, out, out, out, 0, 512);
}